// round 5
// baseline (speedup 1.0000x reference)
#include <cuda_runtime.h>
#include <math.h>
#include <stdint.h>
#include <stddef.h>

#define NN   50000
#define EE   800000
#define LL   16
#define FIN  128
#define DD1  256
#define DD2  64
#define HATT 128

// ---------------- device scratch (no allocations allowed) ----------------
__device__ float g_xw1[NN * DD1];        // x @ W1
__device__ float g_ef [NN * DD1];        // edge features (reused for conv2, first NN*DD2)
__device__ float g_h1 [NN * DD1];        // conv1 output
__device__ float g_xw2[NN * DD2];        // h1 @ W2
__device__ float g_h2 [4 * NN * DD2];    // conv2 outputs per graph
__device__ float g_hye[4 * NN * DD2];    // hyperedge embeddings per graph
__device__ int   g_deg_e[NN], g_deg_n[NN];
__device__ int   g_rp_e[NN + 1], g_rp_n[NN + 1];
__device__ int   g_cur_e[NN], g_cur_n[NN];
__device__ int   g_adj_e[EE], g_adj_n[EE];
__device__ float g_binv[NN], g_dinv[NN];
__device__ float g_S[8];
__device__ float g_beta[8];

// ---------------- small utility kernels ----------------
__global__ void zero_i_kernel(int* p, int n) {
    int i = blockIdx.x * 256 + threadIdx.x;
    if (i < n) p[i] = 0;
}
__global__ void zero_f_kernel(float* p, int n) {
    int i = blockIdx.x * 256 + threadIdx.x;
    if (i < n) p[i] = 0.f;
}

__global__ void hist_kernel(const int* __restrict__ key, int* __restrict__ deg, int e) {
    int p = blockIdx.x * 256 + threadIdx.x;
    if (p < e) atomicAdd(&deg[key[p]], 1);
}

// single-block hierarchical exclusive scan over n ints; writes rp[0..n]
__global__ void scan_kernel(const int* __restrict__ deg, int* __restrict__ rp, int n) {
    __shared__ int wsum[32];
    __shared__ int carry_s;
    int tid = threadIdx.x, lane = tid & 31, w = tid >> 5;
    if (tid == 0) carry_s = 0;
    __syncthreads();
    for (int base = 0; base < n; base += 1024) {
        int i = base + tid;
        int v = (i < n) ? deg[i] : 0;
        int inc = v;
        #pragma unroll
        for (int o = 1; o < 32; o <<= 1) {
            int t = __shfl_up_sync(0xffffffffu, inc, o);
            if (lane >= o) inc += t;
        }
        if (lane == 31) wsum[w] = inc;
        __syncthreads();
        if (w == 0) {
            int x = wsum[lane];
            #pragma unroll
            for (int o = 1; o < 32; o <<= 1) {
                int t = __shfl_up_sync(0xffffffffu, x, o);
                if (lane >= o) x += t;
            }
            wsum[lane] = x;
        }
        __syncthreads();
        int prefix = (w > 0) ? wsum[w - 1] : 0;
        int carry  = carry_s;
        int total  = wsum[31];
        if (i < n) rp[i] = carry + prefix + inc - v;
        __syncthreads();
        if (tid == 0) carry_s = carry + total;
        __syncthreads();
    }
    if (threadIdx.x == 0) rp[n] = carry_s;
}

// cursor := rowptr; inv := 1/deg (0 if deg==0)
__global__ void invcur_kernel(const int* __restrict__ rp, int* __restrict__ cursor,
                              float* __restrict__ inv, int n) {
    int i = blockIdx.x * 256 + threadIdx.x;
    if (i < n) {
        int b = rp[i], e = rp[i + 1];
        cursor[i] = b;
        int d = e - b;
        inv[i] = (d > 0) ? (1.f / (float)d) : 0.f;
    }
}

__global__ void scatter_kernel(const int* __restrict__ key, const int* __restrict__ val,
                               int* __restrict__ cursor, int* __restrict__ adj, int e) {
    int p = blockIdx.x * 256 + threadIdx.x;
    if (p < e) {
        int pos = atomicAdd(&cursor[key[p]], 1);
        adj[pos] = val[p];
    }
}

// ---------------- SGEMM: C[M,Nc] = A[M,K] @ B[K,Nc] ----------------
// BM=BN=128, BK=8, 256 threads, 8x8 microtile
__global__ __launch_bounds__(256) void sgemm_kernel(
    const float* __restrict__ A, const float* __restrict__ B, float* __restrict__ C,
    int M, int K, int Nc)
{
    __shared__ float As[8][132];
    __shared__ float Bs[8][132];
    int bm = blockIdx.y * 128, bn = blockIdx.x * 128;
    int tid = threadIdx.x;
    int tx = tid & 15, ty = tid >> 4;
    float acc[8][8];
    #pragma unroll
    for (int i = 0; i < 8; i++)
        #pragma unroll
        for (int j = 0; j < 8; j++) acc[i][j] = 0.f;

    for (int k0 = 0; k0 < K; k0 += 8) {
        // load A tile (128 x 8)
        #pragma unroll
        for (int i = tid; i < 128 * 8; i += 256) {
            int m = i >> 3, k = i & 7;
            int row = bm + m;
            As[k][m] = (row < M) ? A[(size_t)row * K + (k0 + k)] : 0.f;
        }
        // load B tile (8 x 128)
        #pragma unroll
        for (int i = tid; i < 8 * 128; i += 256) {
            int k = i >> 7, n = i & 127;
            int col = bn + n;
            Bs[k][n] = (col < Nc) ? B[(size_t)(k0 + k) * Nc + col] : 0.f;
        }
        __syncthreads();
        #pragma unroll
        for (int k = 0; k < 8; k++) {
            float a[8], b[8];
            float4 a0 = *(const float4*)&As[k][ty * 8];
            float4 a1 = *(const float4*)&As[k][ty * 8 + 4];
            float4 b0 = *(const float4*)&Bs[k][tx * 8];
            float4 b1 = *(const float4*)&Bs[k][tx * 8 + 4];
            a[0]=a0.x;a[1]=a0.y;a[2]=a0.z;a[3]=a0.w;a[4]=a1.x;a[5]=a1.y;a[6]=a1.z;a[7]=a1.w;
            b[0]=b0.x;b[1]=b0.y;b[2]=b0.z;b[3]=b0.w;b[4]=b1.x;b[5]=b1.y;b[6]=b1.z;b[7]=b1.w;
            #pragma unroll
            for (int i = 0; i < 8; i++)
                #pragma unroll
                for (int j = 0; j < 8; j++)
                    acc[i][j] = fmaf(a[i], b[j], acc[i][j]);
        }
        __syncthreads();
    }
    #pragma unroll
    for (int i = 0; i < 8; i++) {
        int row = bm + ty * 8 + i;
        if (row < M) {
            #pragma unroll
            for (int j = 0; j < 8; j++) {
                int col = bn + tx * 8 + j;
                if (col < Nc) C[(size_t)row * Nc + col] = acc[i][j];
            }
        }
    }
}

// ---------------- segment gather: dst[s] = inv[s] * sum_{i in adj[s]} src[i] (+bias, relu) ----------------
template<int F, bool RELU, bool BIAS>
__global__ void seg_gather_kernel(const int* __restrict__ adj, const int* __restrict__ rp,
                                  const float* __restrict__ inv, const float* __restrict__ src,
                                  float* __restrict__ dst, const float* __restrict__ bias,
                                  int nseg)
{
    constexpr int SPB = 256 / F;
    int s = blockIdx.x * SPB + threadIdx.x / F;
    if (s >= nseg) return;
    int f = threadIdx.x % F;
    int beg = rp[s], end = rp[s + 1];
    float acc = 0.f;
    int i = beg;
    // 2-way unroll for a little MLP on the gather rows
    for (; i + 1 < end; i += 2) {
        int j0 = adj[i], j1 = adj[i + 1];
        acc += src[(size_t)j0 * F + f] + src[(size_t)j1 * F + f];
    }
    if (i < end) acc += src[(size_t)adj[i] * F + f];
    acc *= inv[s];
    if (BIAS) acc += bias[f];
    if (RELU) acc = fmaxf(acc, 0.f);
    dst[(size_t)s * F + f] = acc;
}

// ---------------- hyperedge embedding ----------------
__global__ void hye_kernel(const float* __restrict__ emb, const int* __restrict__ hnode,
                           const float* __restrict__ hlen, float* __restrict__ dst)
{
    int n = blockIdx.x * 4 + threadIdx.x / 64;
    if (n >= NN) return;
    int f = threadIdx.x % 64;
    float acc = 0.f;
    #pragma unroll
    for (int l = 0; l < LL; l++) {
        int v = hnode[n * LL + l];
        if (v > 0) acc += emb[(size_t)(v - 1) * DD2 + f];
    }
    dst[(size_t)n * DD2 + f] = acc / (hlen[n] + 1e-15f);
}

// ---------------- fusion attention ----------------
struct AttnArgs {
    const float* z[8];
    const float* W1[2];
    const float* b1[2];
    const float* W2[2];
};

__global__ __launch_bounds__(128) void attn_kernel(AttnArgs a) {
    __shared__ float sW1[DD2 * HATT];
    __shared__ float sb[HATT];
    __shared__ float sW2[HATT];
    __shared__ float zrow[DD2];
    __shared__ float red[128];
    int comp = blockIdx.y;
    int head = comp >> 2;
    const float* z = a.z[comp];
    int t = threadIdx.x;
    for (int i = t; i < DD2 * HATT; i += 128) sW1[i] = a.W1[head][i];
    sb[t]  = a.b1[head][t];
    sW2[t] = a.W2[head][t];
    __syncthreads();

    float acc = 0.f;
    for (int row = blockIdx.x; row < NN; row += gridDim.x) {
        if (t < DD2) zrow[t] = z[(size_t)row * DD2 + t];
        __syncthreads();
        float h = sb[t];
        #pragma unroll
        for (int f = 0; f < DD2; f++)
            h = fmaf(zrow[f], sW1[f * HATT + t], h);
        acc += tanhf(h) * sW2[t];
        __syncthreads();
    }
    red[t] = acc;
    __syncthreads();
    #pragma unroll
    for (int o = 64; o > 0; o >>= 1) {
        if (t < o) red[t] += red[t + o];
        __syncthreads();
    }
    if (t == 0) atomicAdd(&g_S[comp], red[0]);
}

__global__ void softmax_kernel() {
    if (threadIdx.x == 0 && blockIdx.x == 0) {
        for (int h = 0; h < 2; h++) {
            float v[4];
            float m = -1e30f;
            for (int k = 0; k < 4; k++) { v[k] = g_S[4 * h + k] / (float)NN; m = fmaxf(m, v[k]); }
            float s = 0.f;
            for (int k = 0; k < 4; k++) { v[k] = expf(v[k] - m); s += v[k]; }
            for (int k = 0; k < 4; k++) g_beta[4 * h + k] = v[k] / s;
        }
    }
}

__global__ void combine_kernel(float* __restrict__ out) {
    int idx = blockIdx.x * 256 + threadIdx.x;
    if (idx >= NN * DD2) return;
    __shared__ float b[8];
    if (threadIdx.x < 8) b[threadIdx.x] = g_beta[threadIdx.x];
    __syncthreads();
    const size_t S = (size_t)NN * DD2;
    float c = b[0] * g_h2[1 * S + idx] + b[1] * g_hye[0 * S + idx]
            + b[2] * g_h2[2 * S + idx] + b[3] * g_hye[2 * S + idx];
    float m = b[4] * g_h2[0 * S + idx] + b[5] * g_hye[1 * S + idx]
            + b[6] * g_h2[3 * S + idx] + b[7] * g_hye[3 * S + idx];
    out[idx]     = c;
    out[S + idx] = m;
}

// ---------------- host launcher ----------------
static inline int ceil_div(int a, int b) { return (a + b - 1) / b; }

extern "C" void kernel_launch(void* const* d_in, const int* in_sizes, int n_in,
                              void* d_out, int out_size) {
    (void)out_size;

    // ---- robust input resolution by element count (order-agnostic) ----
    // Size classes (all unambiguous):
    //   x:      NN*FIN   = 6,400,000   (4x, in graph order)
    //   ei:     2*EE     = 1,600,000   (4x)
    //   hnode:  NN*LL    =   800,000   (4x)
    //   hlen:   NN       =    50,000   (4x)
    //   W1:     FIN*DD1  =    32,768
    //   b1:     DD1      =       256
    //   W2:     DD1*DD2  =    16,384
    //   b2:     DD2      =        64
    //   attnW1: DD2*HATT =     8,192   (2x: ac then am)
    //   128-sized (4x, stable order): ac_b1, ac_W2, am_b1, am_W2
    const float* x[4]     = {0,0,0,0};
    const int*   ei[4]    = {0,0,0,0};
    const float* hlen[4]  = {0,0,0,0};
    const int*   hnode[4] = {0,0,0,0};
    const float *W1 = 0, *b1 = 0, *W2 = 0, *b2 = 0;
    const float *aW1[2] = {0,0};
    const float *p128[4] = {0,0,0,0};
    int cx = 0, cei = 0, chn = 0, chl = 0, caw = 0, c128 = 0;
    for (int i = 0; i < n_in; i++) {
        int sz = in_sizes[i];
        const void* p = d_in[i];
        if      (sz == NN * FIN   && cx  < 4) x[cx++]     = (const float*)p;
        else if (sz == 2 * EE     && cei < 4) ei[cei++]   = (const int*)p;
        else if (sz == NN * LL    && chn < 4) hnode[chn++]= (const int*)p;
        else if (sz == NN         && chl < 4) hlen[chl++] = (const float*)p;
        else if (sz == FIN * DD1)             W1 = (const float*)p;
        else if (sz == DD1)                   b1 = (const float*)p;
        else if (sz == DD1 * DD2)             W2 = (const float*)p;
        else if (sz == DD2)                   b2 = (const float*)p;
        else if (sz == DD2 * HATT && caw < 2) aW1[caw++] = (const float*)p;
        else if (sz == HATT       && c128< 4) p128[c128++]= (const float*)p;
    }
    const float* ac_W1 = aW1[0];
    const float* am_W1 = aW1[1];
    const float* ac_b1 = p128[0];
    const float* ac_W2 = p128[1];
    const float* am_b1 = p128[2];
    const float* am_W2 = p128[3];
    float* out = (float*)d_out;

    // resolve device-global scratch addresses (host-side API, capture-safe)
    float *p_xw1, *p_ef, *p_h1, *p_xw2, *p_h2, *p_hye, *p_binv, *p_dinv, *p_S;
    int *p_deg_e, *p_deg_n, *p_rp_e, *p_rp_n, *p_cur_e, *p_cur_n, *p_adj_e, *p_adj_n;
    cudaGetSymbolAddress((void**)&p_xw1,  g_xw1);
    cudaGetSymbolAddress((void**)&p_ef,   g_ef);
    cudaGetSymbolAddress((void**)&p_h1,   g_h1);
    cudaGetSymbolAddress((void**)&p_xw2,  g_xw2);
    cudaGetSymbolAddress((void**)&p_h2,   g_h2);
    cudaGetSymbolAddress((void**)&p_hye,  g_hye);
    cudaGetSymbolAddress((void**)&p_binv, g_binv);
    cudaGetSymbolAddress((void**)&p_dinv, g_dinv);
    cudaGetSymbolAddress((void**)&p_S,    g_S);
    cudaGetSymbolAddress((void**)&p_deg_e, g_deg_e);
    cudaGetSymbolAddress((void**)&p_deg_n, g_deg_n);
    cudaGetSymbolAddress((void**)&p_rp_e,  g_rp_e);
    cudaGetSymbolAddress((void**)&p_rp_n,  g_rp_n);
    cudaGetSymbolAddress((void**)&p_cur_e, g_cur_e);
    cudaGetSymbolAddress((void**)&p_cur_n, g_cur_n);
    cudaGetSymbolAddress((void**)&p_adj_e, g_adj_e);
    cudaGetSymbolAddress((void**)&p_adj_n, g_adj_n);

    const size_t SL = (size_t)NN * DD2;
    const int gridE = ceil_div(EE, 256);
    const int gridN = ceil_div(NN, 256);

    for (int g = 0; g < 4; g++) {
        const int* nidx = ei[g];
        const int* eidx = ei[g] + EE;

        // --- build CSR adjacency (by edge, by node) via counting sort ---
        zero_i_kernel<<<gridN, 256>>>(p_deg_e, NN);
        zero_i_kernel<<<gridN, 256>>>(p_deg_n, NN);
        hist_kernel<<<gridE, 256>>>(eidx, p_deg_e, EE);
        hist_kernel<<<gridE, 256>>>(nidx, p_deg_n, EE);
        scan_kernel<<<1, 1024>>>(p_deg_e, p_rp_e, NN);
        scan_kernel<<<1, 1024>>>(p_deg_n, p_rp_n, NN);
        invcur_kernel<<<gridN, 256>>>(p_rp_e, p_cur_e, p_binv, NN);
        invcur_kernel<<<gridN, 256>>>(p_rp_n, p_cur_n, p_dinv, NN);
        scatter_kernel<<<gridE, 256>>>(eidx, nidx, p_cur_e, p_adj_e, EE);
        scatter_kernel<<<gridE, 256>>>(nidx, eidx, p_cur_n, p_adj_n, EE);

        // --- conv1: xw1 = x @ W1 ; efeat = Binv H^T xw1 ; h1 = relu(Dinv H efeat + b1) ---
        sgemm_kernel<<<dim3(ceil_div(DD1, 128), ceil_div(NN, 128)), 256>>>(x[g], W1, p_xw1, NN, FIN, DD1);
        seg_gather_kernel<DD1, false, false><<<NN, 256>>>(p_adj_e, p_rp_e, p_binv, p_xw1, p_ef, (const float*)0, NN);
        seg_gather_kernel<DD1, true,  true ><<<NN, 256>>>(p_adj_n, p_rp_n, p_dinv, p_ef, p_h1, b1, NN);

        // --- conv2: xw2 = h1 @ W2 ; same two passes with D2=64 ---
        sgemm_kernel<<<dim3(ceil_div(DD2, 128), ceil_div(NN, 128)), 256>>>(p_h1, W2, p_xw2, NN, DD1, DD2);
        seg_gather_kernel<DD2, false, false><<<ceil_div(NN, 4), 256>>>(p_adj_e, p_rp_e, p_binv, p_xw2, p_ef, (const float*)0, NN);
        seg_gather_kernel<DD2, true,  true ><<<ceil_div(NN, 4), 256>>>(p_adj_n, p_rp_n, p_dinv, p_ef, p_h2 + g * SL, b2, NN);

        // --- hyperedge embedding ---
        hye_kernel<<<ceil_div(NN, 4), 256>>>(p_h2 + g * SL, hnode[g], hlen[g], p_hye + g * SL);
    }

    // --- fusion attention ---
    zero_f_kernel<<<1, 256>>>(p_S, 8);
    AttnArgs a;
    a.z[0] = p_h2  + 1 * SL;  // x1_mc
    a.z[1] = p_hye + 0 * SL;  // x2_cm
    a.z[2] = p_h2  + 2 * SL;  // x1_cc
    a.z[3] = p_hye + 2 * SL;  // x2_cc
    a.z[4] = p_h2  + 0 * SL;  // x1_cm
    a.z[5] = p_hye + 1 * SL;  // x2_mc
    a.z[6] = p_h2  + 3 * SL;  // x1_mm
    a.z[7] = p_hye + 3 * SL;  // x2_mm
    a.W1[0] = ac_W1; a.b1[0] = ac_b1; a.W2[0] = ac_W2;
    a.W1[1] = am_W1; a.b1[1] = am_b1; a.W2[1] = am_W2;
    attn_kernel<<<dim3(512, 8), 128>>>(a);
    softmax_kernel<<<1, 32>>>();
    combine_kernel<<<ceil_div(NN * DD2, 256), 256>>>(out);
}

// round 8
// speedup vs baseline: 2.0379x; 2.0379x over previous
#include <cuda_runtime.h>
#include <math.h>
#include <stdint.h>
#include <stddef.h>

#define NN   50000
#define EE   800000
#define LL   16
#define FIN  128
#define DD1  256
#define DD2  64
#define HATT 128
#define NB   49        // ceil(NN / 1024) scan blocks

// ---------------- device scratch (no allocations allowed) ----------------
__device__ float g_y  [NN * FIN];        // double-gathered x (conv1, pre-GEMM)
__device__ float g_ef [NN * FIN];        // edge features (F=128 conv1 / F=64 conv2)
__device__ float g_h1 [NN * DD1];        // conv1 output
__device__ float g_xw2[NN * DD2];        // h1 @ W2
__device__ float g_h2 [4 * NN * DD2];    // conv2 outputs per graph
__device__ float g_hye[4 * NN * DD2];    // hyperedge embeddings per graph
__device__ int   g_deg_e[NN], g_deg_n[NN];
__device__ int   g_rp_e[NN + 1], g_rp_n[NN + 1];
__device__ int   g_cur_e[NN], g_cur_n[NN];
__device__ int   g_adj_e[EE], g_adj_n[EE];
__device__ float g_binv[NN], g_dinv[NN];
__device__ int   g_bsum[2][64];
__device__ float g_S[8];
__device__ float g_beta[8];

static inline int ceil_div(int a, int b) { return (a + b - 1) / b; }

// ---------------- CSR build ----------------
__global__ void zero2_kernel(int* a, int* b, float* s) {
    int i = blockIdx.x * 256 + threadIdx.x;
    if (i < NN) { a[i] = 0; b[i] = 0; }
    if (blockIdx.x == 0 && threadIdx.x < 8) s[threadIdx.x] = 0.f;
}

__global__ void hist2_kernel(const int* __restrict__ nidx, const int* __restrict__ eidx,
                             int* __restrict__ dn, int* __restrict__ de) {
    int p = blockIdx.x * 256 + threadIdx.x;
    if (p < EE) {
        atomicAdd(&dn[nidx[p]], 1);
        atomicAdd(&de[eidx[p]], 1);
    }
}

// block-wide exclusive scan helper (blockDim multiple of 32, <=1024)
__device__ __forceinline__ int block_scan_excl(int v, int* total_out) {
    __shared__ int wsum[32];
    int tid = threadIdx.x, lane = tid & 31, w = tid >> 5;
    int nw = blockDim.x >> 5;
    int inc = v;
    #pragma unroll
    for (int o = 1; o < 32; o <<= 1) {
        int t = __shfl_up_sync(0xffffffffu, inc, o);
        if (lane >= o) inc += t;
    }
    if (lane == 31) wsum[w] = inc;
    __syncthreads();
    if (w == 0) {
        int x = (lane < nw) ? wsum[lane] : 0;
        #pragma unroll
        for (int o = 1; o < 32; o <<= 1) {
            int t = __shfl_up_sync(0xffffffffu, x, o);
            if (lane >= o) x += t;
        }
        wsum[lane] = x;
    }
    __syncthreads();
    int prefix = (w > 0) ? wsum[w - 1] : 0;
    *total_out = wsum[nw - 1];
    int r = prefix + inc - v;
    __syncthreads();
    return r;
}

__global__ void scan_local_kernel(const int* __restrict__ de, const int* __restrict__ dn,
                                  int* __restrict__ rpe, int* __restrict__ rpn) {
    const int* deg = blockIdx.y ? dn : de;
    int* rp = blockIdx.y ? rpn : rpe;
    int i = blockIdx.x * 1024 + threadIdx.x;
    int v = (i < NN) ? deg[i] : 0;
    int total;
    int ex = block_scan_excl(v, &total);
    if (i < NN) rp[i] = ex;
    if (threadIdx.x == 0) g_bsum[blockIdx.y][blockIdx.x] = total;
}

__global__ void scan_spine_kernel() {
    int y = blockIdx.x;
    int t = threadIdx.x;
    int v = (t < NB) ? g_bsum[y][t] : 0;
    int total;
    int ex = block_scan_excl(v, &total);
    if (t < NB) g_bsum[y][t] = ex;
}

__global__ void scan_add_kernel(const int* __restrict__ de, const int* __restrict__ dn,
                                int* __restrict__ rpe, int* __restrict__ rpn,
                                int* __restrict__ cure, int* __restrict__ curn,
                                float* __restrict__ binv, float* __restrict__ dinv) {
    int i = blockIdx.x * 1024 + threadIdx.x;
    if (i >= NN) return;
    int off = g_bsum[blockIdx.y][blockIdx.x];
    if (blockIdx.y == 0) {
        int r = rpe[i] + off;
        rpe[i] = r; cure[i] = r;
        int d = de[i];
        binv[i] = (d > 0) ? (1.f / (float)d) : 0.f;
        if (i == NN - 1) rpe[NN] = r + d;
    } else {
        int r = rpn[i] + off;
        rpn[i] = r; curn[i] = r;
        int d = dn[i];
        dinv[i] = (d > 0) ? (1.f / (float)d) : 0.f;
        if (i == NN - 1) rpn[NN] = r + d;
    }
}

__global__ void scatter2_kernel(const int* __restrict__ nidx, const int* __restrict__ eidx,
                                int* __restrict__ cure, int* __restrict__ curn,
                                int* __restrict__ adje, int* __restrict__ adjn) {
    int p = blockIdx.x * 256 + threadIdx.x;
    if (p >= EE) return;
    int nv = nidx[p], ev = eidx[p];
    int pe = atomicAdd(&cure[ev], 1); adje[pe] = nv;
    int pn = atomicAdd(&curn[nv], 1); adjn[pn] = ev;
}

// ---------------- SGEMM: C[M,Nc] = A[M,K] @ B[K,Nc], optional bias+relu ----------------
// 256 threads, 8x8 microtile, BK=16, register-prefetch pipeline.
template<int BM, int BN, bool EPI>
__global__ __launch_bounds__(256) void sgemm_kernel(
    const float* __restrict__ A, const float* __restrict__ B,
    float* __restrict__ C, const float* __restrict__ bias,
    int M, int K, int Nc)
{
    constexpr int BK = 16;
    constexpr int A_PT = BM * BK / (4 * 256);
    constexpr int B_PT = BK * BN / (4 * 256);
    constexpr int TX = BN / 8;
    __shared__ float As[BK][BM + 4];
    __shared__ float Bs[BK][BN + 4];
    const int bm = blockIdx.y * BM, bn = blockIdx.x * BN;
    const int tid = threadIdx.x;
    const int tx = tid % TX, ty = tid / TX;

    float4 aReg[A_PT], bReg[B_PT];
    #pragma unroll
    for (int p = 0; p < A_PT; p++) {
        int idx = tid + p * 256;
        int r = idx >> 2, kq = (idx & 3) * 4;
        int row = bm + r;
        aReg[p] = (row < M) ? *(const float4*)&A[(size_t)row * K + kq]
                            : make_float4(0.f, 0.f, 0.f, 0.f);
    }
    #pragma unroll
    for (int p = 0; p < B_PT; p++) {
        int idx = tid + p * 256;
        int kr = idx / (BN / 4), nq = (idx % (BN / 4)) * 4;
        bReg[p] = *(const float4*)&B[(size_t)kr * Nc + bn + nq];
    }

    float acc[8][8];
    #pragma unroll
    for (int i = 0; i < 8; i++)
        #pragma unroll
        for (int j = 0; j < 8; j++) acc[i][j] = 0.f;

    const int nk = K / BK;
    for (int t = 0; t < nk; t++) {
        #pragma unroll
        for (int p = 0; p < A_PT; p++) {
            int idx = tid + p * 256;
            int r = idx >> 2, kq = (idx & 3) * 4;
            As[kq + 0][r] = aReg[p].x;
            As[kq + 1][r] = aReg[p].y;
            As[kq + 2][r] = aReg[p].z;
            As[kq + 3][r] = aReg[p].w;
        }
        #pragma unroll
        for (int p = 0; p < B_PT; p++) {
            int idx = tid + p * 256;
            int kr = idx / (BN / 4), nq = (idx % (BN / 4)) * 4;
            *(float4*)&Bs[kr][nq] = bReg[p];
        }
        __syncthreads();
        if (t + 1 < nk) {
            int k0 = (t + 1) * BK;
            #pragma unroll
            for (int p = 0; p < A_PT; p++) {
                int idx = tid + p * 256;
                int r = idx >> 2, kq = (idx & 3) * 4;
                int row = bm + r;
                aReg[p] = (row < M) ? *(const float4*)&A[(size_t)row * K + k0 + kq]
                                    : make_float4(0.f, 0.f, 0.f, 0.f);
            }
            #pragma unroll
            for (int p = 0; p < B_PT; p++) {
                int idx = tid + p * 256;
                int kr = idx / (BN / 4), nq = (idx % (BN / 4)) * 4;
                bReg[p] = *(const float4*)&B[(size_t)(k0 + kr) * Nc + bn + nq];
            }
        }
        #pragma unroll
        for (int k = 0; k < BK; k++) {
            float4 a0 = *(const float4*)&As[k][ty * 8];
            float4 a1 = *(const float4*)&As[k][ty * 8 + 4];
            float4 b0 = *(const float4*)&Bs[k][tx * 8];
            float4 b1 = *(const float4*)&Bs[k][tx * 8 + 4];
            float av[8] = {a0.x,a0.y,a0.z,a0.w,a1.x,a1.y,a1.z,a1.w};
            float bv[8] = {b0.x,b0.y,b0.z,b0.w,b1.x,b1.y,b1.z,b1.w};
            #pragma unroll
            for (int i = 0; i < 8; i++)
                #pragma unroll
                for (int j = 0; j < 8; j++)
                    acc[i][j] = fmaf(av[i], bv[j], acc[i][j]);
        }
        __syncthreads();
    }

    int colb = bn + tx * 8;
    float bv[8];
    if (EPI) {
        #pragma unroll
        for (int j = 0; j < 8; j++) bv[j] = bias[colb + j];
    }
    #pragma unroll
    for (int i = 0; i < 8; i++) {
        int row = bm + ty * 8 + i;
        if (row < M) {
            float v[8];
            #pragma unroll
            for (int j = 0; j < 8; j++) {
                float t = acc[i][j];
                if (EPI) t = fmaxf(t + bv[j], 0.f);
                v[j] = t;
            }
            *(float4*)&C[(size_t)row * Nc + colb]     = make_float4(v[0], v[1], v[2], v[3]);
            *(float4*)&C[(size_t)row * Nc + colb + 4] = make_float4(v[4], v[5], v[6], v[7]);
        }
    }
}

// ---------------- segment gather (vectorized): dst[s] = inv[s]*sum src[adj] (+bias,relu) ----------------
template<int F, bool RELU, bool BIAS>
__global__ void seg_gather_kernel(const int* __restrict__ adj, const int* __restrict__ rp,
                                  const float* __restrict__ inv, const float* __restrict__ src,
                                  float* __restrict__ dst, const float* __restrict__ bias,
                                  int nseg)
{
    constexpr int T = F / 4;           // threads per segment (float4 lanes)
    constexpr int SPB = 256 / T;
    int s = blockIdx.x * SPB + threadIdx.x / T;
    if (s >= nseg) return;
    int f4 = (threadIdx.x % T) * 4;
    int beg = rp[s], end = rp[s + 1];
    float4 acc = make_float4(0.f, 0.f, 0.f, 0.f);
    int i = beg;
    for (; i + 4 <= end; i += 4) {
        int j0 = adj[i], j1 = adj[i+1], j2 = adj[i+2], j3 = adj[i+3];
        float4 a = *(const float4*)&src[(size_t)j0 * F + f4];
        float4 b = *(const float4*)&src[(size_t)j1 * F + f4];
        float4 c = *(const float4*)&src[(size_t)j2 * F + f4];
        float4 d = *(const float4*)&src[(size_t)j3 * F + f4];
        acc.x += (a.x + b.x) + (c.x + d.x);
        acc.y += (a.y + b.y) + (c.y + d.y);
        acc.z += (a.z + b.z) + (c.z + d.z);
        acc.w += (a.w + b.w) + (c.w + d.w);
    }
    for (; i < end; i++) {
        float4 a = *(const float4*)&src[(size_t)adj[i] * F + f4];
        acc.x += a.x; acc.y += a.y; acc.z += a.z; acc.w += a.w;
    }
    float sc = inv[s];
    acc.x *= sc; acc.y *= sc; acc.z *= sc; acc.w *= sc;
    if (BIAS) {
        float4 bb = *(const float4*)&bias[f4];
        acc.x += bb.x; acc.y += bb.y; acc.z += bb.z; acc.w += bb.w;
    }
    if (RELU) {
        acc.x = fmaxf(acc.x, 0.f); acc.y = fmaxf(acc.y, 0.f);
        acc.z = fmaxf(acc.z, 0.f); acc.w = fmaxf(acc.w, 0.f);
    }
    *(float4*)&dst[(size_t)s * F + f4] = acc;
}

// ---------------- hyperedge embedding (vectorized) ----------------
__global__ void hye_kernel(const float* __restrict__ emb, const int* __restrict__ hnode,
                           const float* __restrict__ hlen, float* __restrict__ dst)
{
    int n = blockIdx.x * 16 + threadIdx.x / 16;
    if (n >= NN) return;
    int f4 = (threadIdx.x % 16) * 4;
    float4 acc = make_float4(0.f, 0.f, 0.f, 0.f);
    #pragma unroll
    for (int l = 0; l < LL; l++) {
        int v = hnode[n * LL + l];
        if (v > 0) {
            float4 e = *(const float4*)&emb[(size_t)(v - 1) * DD2 + f4];
            acc.x += e.x; acc.y += e.y; acc.z += e.z; acc.w += e.w;
        }
    }
    float s = 1.f / (hlen[n] + 1e-15f);
    *(float4*)&dst[(size_t)n * DD2 + f4] =
        make_float4(acc.x * s, acc.y * s, acc.z * s, acc.w * s);
}

// ---------------- fusion attention (8 rows per iter, FMA-bound) ----------------
struct AttnArgs {
    const float* z[8];
    const float* W1[2];
    const float* b1[2];
    const float* W2[2];
};

__global__ __launch_bounds__(128) void attn_kernel(AttnArgs a) {
    __shared__ float sW1[DD2 * HATT];
    __shared__ float sb[HATT];
    __shared__ float sW2[HATT];
    __shared__ float Zs[DD2][12];       // 8 rows used, pad 12 keeps float4 alignment
    __shared__ float red[128];
    int comp = blockIdx.y;
    int head = comp >> 2;
    const float* z = a.z[comp];
    int t = threadIdx.x;
    for (int i = t; i < DD2 * HATT; i += 128) sW1[i] = a.W1[head][i];
    sb[t]  = a.b1[head][t];
    sW2[t] = a.W2[head][t];
    __syncthreads();

    float acc = 0.f;
    float w2 = sW2[t];
    for (int row0 = blockIdx.x * 8; row0 < NN; row0 += gridDim.x * 8) {
        #pragma unroll
        for (int j = 0; j < 4; j++) {
            int idx = t + 128 * j;        // 0..511
            int f = idx & 63, r = idx >> 6;
            Zs[f][r] = z[(size_t)(row0 + r) * DD2 + f];
        }
        __syncthreads();
        float h[8];
        #pragma unroll
        for (int r = 0; r < 8; r++) h[r] = sb[t];
        #pragma unroll 8
        for (int f = 0; f < DD2; f++) {
            float w = sW1[f * HATT + t];
            float4 za = *(const float4*)&Zs[f][0];
            float4 zb = *(const float4*)&Zs[f][4];
            h[0] = fmaf(za.x, w, h[0]); h[1] = fmaf(za.y, w, h[1]);
            h[2] = fmaf(za.z, w, h[2]); h[3] = fmaf(za.w, w, h[3]);
            h[4] = fmaf(zb.x, w, h[4]); h[5] = fmaf(zb.y, w, h[5]);
            h[6] = fmaf(zb.z, w, h[6]); h[7] = fmaf(zb.w, w, h[7]);
        }
        #pragma unroll
        for (int r = 0; r < 8; r++) acc += tanhf(h[r]) * w2;
        __syncthreads();
    }
    red[t] = acc;
    __syncthreads();
    #pragma unroll
    for (int o = 64; o > 0; o >>= 1) {
        if (t < o) red[t] += red[t + o];
        __syncthreads();
    }
    if (t == 0) atomicAdd(&g_S[comp], red[0]);
}

__global__ void softmax_kernel() {
    if (threadIdx.x == 0 && blockIdx.x == 0) {
        for (int h = 0; h < 2; h++) {
            float v[4];
            float m = -1e30f;
            for (int k = 0; k < 4; k++) { v[k] = g_S[4 * h + k] / (float)NN; m = fmaxf(m, v[k]); }
            float s = 0.f;
            for (int k = 0; k < 4; k++) { v[k] = expf(v[k] - m); s += v[k]; }
            for (int k = 0; k < 4; k++) g_beta[4 * h + k] = v[k] / s;
        }
    }
}

__global__ void combine_kernel(float* __restrict__ out) {
    int idx = blockIdx.x * 256 + threadIdx.x;
    if (idx >= NN * DD2) return;
    __shared__ float b[8];
    if (threadIdx.x < 8) b[threadIdx.x] = g_beta[threadIdx.x];
    __syncthreads();
    const size_t S = (size_t)NN * DD2;
    float c = b[0] * g_h2[1 * S + idx] + b[1] * g_hye[0 * S + idx]
            + b[2] * g_h2[2 * S + idx] + b[3] * g_hye[2 * S + idx];
    float m = b[4] * g_h2[0 * S + idx] + b[5] * g_hye[1 * S + idx]
            + b[6] * g_h2[3 * S + idx] + b[7] * g_hye[3 * S + idx];
    out[idx]     = c;
    out[S + idx] = m;
}

// ---------------- host launcher ----------------
extern "C" void kernel_launch(void* const* d_in, const int* in_sizes, int n_in,
                              void* d_out, int out_size) {
    (void)out_size;

    // ---- input resolution by element count (order-agnostic) ----
    const float* x[4]     = {0,0,0,0};
    const int*   ei[4]    = {0,0,0,0};
    const float* hlen[4]  = {0,0,0,0};
    const int*   hnode[4] = {0,0,0,0};
    const float *W1 = 0, *b1 = 0, *W2 = 0, *b2 = 0;
    const float *aW1[2] = {0,0};
    const float *p128[4] = {0,0,0,0};
    int cx = 0, cei = 0, chn = 0, chl = 0, caw = 0, c128 = 0;
    for (int i = 0; i < n_in; i++) {
        int sz = in_sizes[i];
        const void* p = d_in[i];
        if      (sz == NN * FIN   && cx  < 4) x[cx++]      = (const float*)p;
        else if (sz == 2 * EE     && cei < 4) ei[cei++]    = (const int*)p;
        else if (sz == NN * LL    && chn < 4) hnode[chn++] = (const int*)p;
        else if (sz == NN         && chl < 4) hlen[chl++]  = (const float*)p;
        else if (sz == FIN * DD1)             W1 = (const float*)p;
        else if (sz == DD1)                   b1 = (const float*)p;
        else if (sz == DD1 * DD2)             W2 = (const float*)p;
        else if (sz == DD2)                   b2 = (const float*)p;
        else if (sz == DD2 * HATT && caw < 2) aW1[caw++]   = (const float*)p;
        else if (sz == HATT       && c128< 4) p128[c128++] = (const float*)p;
    }
    const float* ac_W1 = aW1[0];
    const float* am_W1 = aW1[1];
    const float* ac_b1 = p128[0];
    const float* ac_W2 = p128[1];
    const float* am_b1 = p128[2];
    const float* am_W2 = p128[3];
    float* out = (float*)d_out;

    float *p_y, *p_ef, *p_h1, *p_xw2, *p_h2, *p_hye, *p_binv, *p_dinv, *p_S;
    int *p_deg_e, *p_deg_n, *p_rp_e, *p_rp_n, *p_cur_e, *p_cur_n, *p_adj_e, *p_adj_n;
    cudaGetSymbolAddress((void**)&p_y,    g_y);
    cudaGetSymbolAddress((void**)&p_ef,   g_ef);
    cudaGetSymbolAddress((void**)&p_h1,   g_h1);
    cudaGetSymbolAddress((void**)&p_xw2,  g_xw2);
    cudaGetSymbolAddress((void**)&p_h2,   g_h2);
    cudaGetSymbolAddress((void**)&p_hye,  g_hye);
    cudaGetSymbolAddress((void**)&p_binv, g_binv);
    cudaGetSymbolAddress((void**)&p_dinv, g_dinv);
    cudaGetSymbolAddress((void**)&p_S,    g_S);
    cudaGetSymbolAddress((void**)&p_deg_e, g_deg_e);
    cudaGetSymbolAddress((void**)&p_deg_n, g_deg_n);
    cudaGetSymbolAddress((void**)&p_rp_e,  g_rp_e);
    cudaGetSymbolAddress((void**)&p_rp_n,  g_rp_n);
    cudaGetSymbolAddress((void**)&p_cur_e, g_cur_e);
    cudaGetSymbolAddress((void**)&p_cur_n, g_cur_n);
    cudaGetSymbolAddress((void**)&p_adj_e, g_adj_e);
    cudaGetSymbolAddress((void**)&p_adj_n, g_adj_n);

    const size_t SL = (size_t)NN * DD2;
    const int gridE = ceil_div(EE, 256);
    const int gridN = ceil_div(NN, 256);

    for (int g = 0; g < 4; g++) {
        const int* nidx = ei[g];
        const int* eidx = ei[g] + EE;

        // --- CSR build (counting sort, parallel scan) ---
        zero2_kernel<<<gridN, 256>>>(p_deg_e, p_deg_n, p_S);
        hist2_kernel<<<gridE, 256>>>(nidx, eidx, p_deg_n, p_deg_e);
        scan_local_kernel<<<dim3(NB, 2), 1024>>>(p_deg_e, p_deg_n, p_rp_e, p_rp_n);
        scan_spine_kernel<<<2, 64>>>();
        scan_add_kernel<<<dim3(NB, 2), 1024>>>(p_deg_e, p_deg_n, p_rp_e, p_rp_n,
                                               p_cur_e, p_cur_n, p_binv, p_dinv);
        scatter2_kernel<<<gridE, 256>>>(nidx, eidx, p_cur_e, p_cur_n, p_adj_e, p_adj_n);

        // --- conv1 (reordered): y = Dinv H Binv H^T x at F=128, then h1 = relu(y@W1 + b1) ---
        seg_gather_kernel<FIN, false, false><<<ceil_div(NN, 8), 256>>>(
            p_adj_e, p_rp_e, p_binv, x[g], p_ef, (const float*)0, NN);
        seg_gather_kernel<FIN, false, false><<<ceil_div(NN, 8), 256>>>(
            p_adj_n, p_rp_n, p_dinv, p_ef, p_y, (const float*)0, NN);
        sgemm_kernel<128, 128, true><<<dim3(DD1 / 128, ceil_div(NN, 128)), 256>>>(
            p_y, W1, p_h1, b1, NN, FIN, DD1);

        // --- conv2: xw2 = h1@W2, then two gathers at F=64 ---
        sgemm_kernel<256, 64, false><<<dim3(1, ceil_div(NN, 256)), 256>>>(
            p_h1, W2, p_xw2, (const float*)0, NN, DD1, DD2);
        seg_gather_kernel<DD2, false, false><<<ceil_div(NN, 16), 256>>>(
            p_adj_e, p_rp_e, p_binv, p_xw2, p_ef, (const float*)0, NN);
        seg_gather_kernel<DD2, true, true><<<ceil_div(NN, 16), 256>>>(
            p_adj_n, p_rp_n, p_dinv, p_ef, p_h2 + g * SL, b2, NN);

        // --- hyperedge embedding ---
        hye_kernel<<<ceil_div(NN, 16), 256>>>(p_h2 + g * SL, hnode[g], hlen[g], p_hye + g * SL);
    }

    // --- fusion attention ---
    AttnArgs a;
    a.z[0] = p_h2  + 1 * SL;  // x1_mc
    a.z[1] = p_hye + 0 * SL;  // x2_cm
    a.z[2] = p_h2  + 2 * SL;  // x1_cc
    a.z[3] = p_hye + 2 * SL;  // x2_cc
    a.z[4] = p_h2  + 0 * SL;  // x1_cm
    a.z[5] = p_hye + 1 * SL;  // x2_mc
    a.z[6] = p_h2  + 3 * SL;  // x1_mm
    a.z[7] = p_hye + 3 * SL;  // x2_mm
    a.W1[0] = ac_W1; a.b1[0] = ac_b1; a.W2[0] = ac_W2;
    a.W1[1] = am_W1; a.b1[1] = am_b1; a.W2[1] = am_W2;
    attn_kernel<<<dim3(148, 8), 128>>>(a);
    softmax_kernel<<<1, 32>>>();
    combine_kernel<<<ceil_div(NN * DD2, 256), 256>>>(out);
}

// round 9
// speedup vs baseline: 2.1490x; 1.0545x over previous
#include <cuda_runtime.h>
#include <math.h>
#include <stdint.h>
#include <stddef.h>

#define NN   50000
#define EE   800000
#define LL   16
#define FIN  128
#define DD1  256
#define DD2  64
#define HATT 128
#define NB   49        // ceil(NN / 1024) scan blocks

typedef unsigned long long u64;

// ---------------- f32x2 packed helpers (sm_103a) ----------------
__device__ __forceinline__ u64 pack_dup(float a) {
    u64 d; unsigned int ai = __float_as_uint(a);
    asm("mov.b64 %0, {%1, %1};" : "=l"(d) : "r"(ai));
    return d;
}
__device__ __forceinline__ void fma2(u64& d, u64 a, u64 b) {
    asm("fma.rn.f32x2 %0, %1, %2, %0;" : "+l"(d) : "l"(a), "l"(b));
}
__device__ __forceinline__ float2 unpack2(u64 v) {
    unsigned int lo, hi;
    asm("mov.b64 {%0, %1}, %2;" : "=r"(lo), "=r"(hi) : "l"(v));
    return make_float2(__uint_as_float(lo), __uint_as_float(hi));
}

// ---------------- device scratch (no allocations allowed) ----------------
__device__ float g_y  [4 * NN * FIN];    // double-gathered x per graph
__device__ float g_ef [NN * FIN];        // edge features (reused)
__device__ float g_h1 [4 * NN * DD1];    // conv1 outputs per graph
__device__ float g_xw2[4 * NN * DD2];    // h1 @ W2 per graph
__device__ float g_h2 [4 * NN * DD2];    // conv2 outputs per graph
__device__ float g_hye[4 * NN * DD2];    // hyperedge embeddings per graph
__device__ int   g_deg_e[4 * NN], g_deg_n[4 * NN];
__device__ int   g_rp_e[4 * (NN + 1)], g_rp_n[4 * (NN + 1)];
__device__ int   g_cur_e[4 * NN], g_cur_n[4 * NN];
__device__ int   g_adj_e[4 * EE], g_adj_n[4 * EE];
__device__ float g_binv[4 * NN], g_dinv[4 * NN];
__device__ int   g_bsum[8][64];
__device__ float g_S[8];
__device__ float g_beta[8];

static inline int ceil_div(int a, int b) { return (a + b - 1) / b; }

struct EiArgs { const int* nidx[4]; const int* eidx[4]; };
struct HyeArgs { const int* hnode[4]; const float* hlen[4]; };
struct GemmB { const float* A[4]; float* C[4]; };

// ---------------- CSR build (batched over 4 graphs) ----------------
__global__ void zero_all_kernel(int* de, int* dn, float* s) {
    int i = blockIdx.x * 256 + threadIdx.x;
    if (i < 4 * NN) { de[i] = 0; dn[i] = 0; }
    if (blockIdx.x == 0 && threadIdx.x < 8) s[threadIdx.x] = 0.f;
}

__global__ void hist2_all_kernel(EiArgs a, int* __restrict__ dn, int* __restrict__ de) {
    int g = blockIdx.y;
    int p = blockIdx.x * 256 + threadIdx.x;
    if (p < EE) {
        atomicAdd(&dn[g * NN + a.nidx[g][p]], 1);
        atomicAdd(&de[g * NN + a.eidx[g][p]], 1);
    }
}

__device__ __forceinline__ int block_scan_excl(int v, int* total_out) {
    __shared__ int wsum[32];
    int tid = threadIdx.x, lane = tid & 31, w = tid >> 5;
    int nw = blockDim.x >> 5;
    int inc = v;
    #pragma unroll
    for (int o = 1; o < 32; o <<= 1) {
        int t = __shfl_up_sync(0xffffffffu, inc, o);
        if (lane >= o) inc += t;
    }
    if (lane == 31) wsum[w] = inc;
    __syncthreads();
    if (w == 0) {
        int x = (lane < nw) ? wsum[lane] : 0;
        #pragma unroll
        for (int o = 1; o < 32; o <<= 1) {
            int t = __shfl_up_sync(0xffffffffu, x, o);
            if (lane >= o) x += t;
        }
        wsum[lane] = x;
    }
    __syncthreads();
    int prefix = (w > 0) ? wsum[w - 1] : 0;
    *total_out = wsum[nw - 1];
    int r = prefix + inc - v;
    __syncthreads();
    return r;
}

// y in [0,8): kind = y>>2 (0=e,1=n), graph = y&3
__global__ void scan_local_all_kernel(const int* __restrict__ de, const int* __restrict__ dn,
                                      int* __restrict__ rpe, int* __restrict__ rpn) {
    int y = blockIdx.y;
    int g = y & 3, kind = y >> 2;
    const int* deg = (kind ? dn : de) + g * NN;
    int* rp = (kind ? rpn : rpe) + g * (NN + 1);
    int i = blockIdx.x * 1024 + threadIdx.x;
    int v = (i < NN) ? deg[i] : 0;
    int total;
    int ex = block_scan_excl(v, &total);
    if (i < NN) rp[i] = ex;
    if (threadIdx.x == 0) g_bsum[y][blockIdx.x] = total;
}

__global__ void scan_spine_all_kernel() {
    int y = blockIdx.x;
    int t = threadIdx.x;
    int v = (t < NB) ? g_bsum[y][t] : 0;
    int total;
    int ex = block_scan_excl(v, &total);
    if (t < NB) g_bsum[y][t] = ex;
}

__global__ void scan_add_all_kernel(const int* __restrict__ de, const int* __restrict__ dn,
                                    int* __restrict__ rpe, int* __restrict__ rpn,
                                    int* __restrict__ cure, int* __restrict__ curn,
                                    float* __restrict__ binv, float* __restrict__ dinv) {
    int y = blockIdx.y;
    int g = y & 3, kind = y >> 2;
    int i = blockIdx.x * 1024 + threadIdx.x;
    if (i >= NN) return;
    int off = g_bsum[y][blockIdx.x];
    const int* deg = (kind ? dn : de) + g * NN;
    int* rp  = (kind ? rpn : rpe) + g * (NN + 1);
    int* cur = (kind ? curn : cure) + g * NN;
    float* inv = (kind ? dinv : binv) + g * NN;
    int r = rp[i] + off;
    rp[i] = r; cur[i] = r;
    int d = deg[i];
    inv[i] = (d > 0) ? (1.f / (float)d) : 0.f;
    if (i == NN - 1) rp[NN] = r + d;
}

__global__ void scatter2_all_kernel(EiArgs a, int* __restrict__ cure, int* __restrict__ curn,
                                    int* __restrict__ adje, int* __restrict__ adjn) {
    int g = blockIdx.y;
    int p = blockIdx.x * 256 + threadIdx.x;
    if (p >= EE) return;
    int nv = a.nidx[g][p], ev = a.eidx[g][p];
    int pe = atomicAdd(&cure[g * NN + ev], 1); adje[(size_t)g * EE + pe] = nv;
    int pn = atomicAdd(&curn[g * NN + nv], 1); adjn[(size_t)g * EE + pn] = ev;
}

// ---------------- SGEMM (f32x2 packed), batched over graphs via blockIdx.z ----------------
template<int BM, int BN, bool EPI>
__global__ __launch_bounds__(256) void sgemm_kernel(
    GemmB gp, const float* __restrict__ B, const float* __restrict__ bias,
    int M, int K, int Nc)
{
    constexpr int BK = 16;
    constexpr int A_PT = BM * BK / (4 * 256);
    constexpr int B_PT = BK * BN / (4 * 256);
    constexpr int TX = BN / 8;
    __shared__ __align__(16) float As[BK][BM + 4];
    __shared__ __align__(16) float Bs[BK][BN + 4];
    const float* __restrict__ A = gp.A[blockIdx.z];
    float* __restrict__ C = gp.C[blockIdx.z];
    const int bm = blockIdx.y * BM, bn = blockIdx.x * BN;
    const int tid = threadIdx.x;
    const int tx = tid % TX, ty = tid / TX;

    float4 aReg[A_PT], bReg[B_PT];
    #pragma unroll
    for (int p = 0; p < A_PT; p++) {
        int idx = tid + p * 256;
        int r = idx >> 2, kq = (idx & 3) * 4;
        int row = bm + r;
        aReg[p] = (row < M) ? *(const float4*)&A[(size_t)row * K + kq]
                            : make_float4(0.f, 0.f, 0.f, 0.f);
    }
    #pragma unroll
    for (int p = 0; p < B_PT; p++) {
        int idx = tid + p * 256;
        int kr = idx / (BN / 4), nq = (idx % (BN / 4)) * 4;
        bReg[p] = *(const float4*)&B[(size_t)kr * Nc + bn + nq];
    }

    u64 acc[8][4];
    #pragma unroll
    for (int i = 0; i < 8; i++)
        #pragma unroll
        for (int j = 0; j < 4; j++) acc[i][j] = 0ull;

    const int nk = K / BK;
    for (int t = 0; t < nk; t++) {
        #pragma unroll
        for (int p = 0; p < A_PT; p++) {
            int idx = tid + p * 256;
            int r = idx >> 2, kq = (idx & 3) * 4;
            As[kq + 0][r] = aReg[p].x;
            As[kq + 1][r] = aReg[p].y;
            As[kq + 2][r] = aReg[p].z;
            As[kq + 3][r] = aReg[p].w;
        }
        #pragma unroll
        for (int p = 0; p < B_PT; p++) {
            int idx = tid + p * 256;
            int kr = idx / (BN / 4), nq = (idx % (BN / 4)) * 4;
            *(float4*)&Bs[kr][nq] = bReg[p];
        }
        __syncthreads();
        if (t + 1 < nk) {
            int k0 = (t + 1) * BK;
            #pragma unroll
            for (int p = 0; p < A_PT; p++) {
                int idx = tid + p * 256;
                int r = idx >> 2, kq = (idx & 3) * 4;
                int row = bm + r;
                aReg[p] = (row < M) ? *(const float4*)&A[(size_t)row * K + k0 + kq]
                                    : make_float4(0.f, 0.f, 0.f, 0.f);
            }
            #pragma unroll
            for (int p = 0; p < B_PT; p++) {
                int idx = tid + p * 256;
                int kr = idx / (BN / 4), nq = (idx % (BN / 4)) * 4;
                bReg[p] = *(const float4*)&B[(size_t)(k0 + kr) * Nc + bn + nq];
            }
        }
        #pragma unroll
        for (int k = 0; k < BK; k++) {
            float4 a0 = *(const float4*)&As[k][ty * 8];
            float4 a1 = *(const float4*)&As[k][ty * 8 + 4];
            ulonglong2 bb0 = *(const ulonglong2*)&Bs[k][tx * 8];
            ulonglong2 bb1 = *(const ulonglong2*)&Bs[k][tx * 8 + 4];
            float av[8] = {a0.x, a0.y, a0.z, a0.w, a1.x, a1.y, a1.z, a1.w};
            #pragma unroll
            for (int i = 0; i < 8; i++) {
                u64 ad = pack_dup(av[i]);
                fma2(acc[i][0], ad, bb0.x);
                fma2(acc[i][1], ad, bb0.y);
                fma2(acc[i][2], ad, bb1.x);
                fma2(acc[i][3], ad, bb1.y);
            }
        }
        __syncthreads();
    }

    int colb = bn + tx * 8;
    float bv[8];
    if (EPI) {
        #pragma unroll
        for (int j = 0; j < 8; j++) bv[j] = bias[colb + j];
    }
    #pragma unroll
    for (int i = 0; i < 8; i++) {
        int row = bm + ty * 8 + i;
        if (row < M) {
            float v[8];
            #pragma unroll
            for (int jp = 0; jp < 4; jp++) {
                float2 c = unpack2(acc[i][jp]);
                v[2 * jp] = c.x; v[2 * jp + 1] = c.y;
            }
            if (EPI) {
                #pragma unroll
                for (int j = 0; j < 8; j++) v[j] = fmaxf(v[j] + bv[j], 0.f);
            }
            *(float4*)&C[(size_t)row * Nc + colb]     = make_float4(v[0], v[1], v[2], v[3]);
            *(float4*)&C[(size_t)row * Nc + colb + 4] = make_float4(v[4], v[5], v[6], v[7]);
        }
    }
}

// ---------------- segment gather (vectorized) ----------------
template<int F, bool RELU, bool BIAS>
__global__ void seg_gather_kernel(const int* __restrict__ adj, const int* __restrict__ rp,
                                  const float* __restrict__ inv, const float* __restrict__ src,
                                  float* __restrict__ dst, const float* __restrict__ bias,
                                  int nseg)
{
    constexpr int T = F / 4;
    constexpr int SPB = 256 / T;
    int s = blockIdx.x * SPB + threadIdx.x / T;
    if (s >= nseg) return;
    int f4 = (threadIdx.x % T) * 4;
    int beg = rp[s], end = rp[s + 1];
    float4 acc = make_float4(0.f, 0.f, 0.f, 0.f);
    int i = beg;
    for (; i + 4 <= end; i += 4) {
        int j0 = adj[i], j1 = adj[i+1], j2 = adj[i+2], j3 = adj[i+3];
        float4 a = *(const float4*)&src[(size_t)j0 * F + f4];
        float4 b = *(const float4*)&src[(size_t)j1 * F + f4];
        float4 c = *(const float4*)&src[(size_t)j2 * F + f4];
        float4 d = *(const float4*)&src[(size_t)j3 * F + f4];
        acc.x += (a.x + b.x) + (c.x + d.x);
        acc.y += (a.y + b.y) + (c.y + d.y);
        acc.z += (a.z + b.z) + (c.z + d.z);
        acc.w += (a.w + b.w) + (c.w + d.w);
    }
    for (; i < end; i++) {
        float4 a = *(const float4*)&src[(size_t)adj[i] * F + f4];
        acc.x += a.x; acc.y += a.y; acc.z += a.z; acc.w += a.w;
    }
    float sc = inv[s];
    acc.x *= sc; acc.y *= sc; acc.z *= sc; acc.w *= sc;
    if (BIAS) {
        float4 bb = *(const float4*)&bias[f4];
        acc.x += bb.x; acc.y += bb.y; acc.z += bb.z; acc.w += bb.w;
    }
    if (RELU) {
        acc.x = fmaxf(acc.x, 0.f); acc.y = fmaxf(acc.y, 0.f);
        acc.z = fmaxf(acc.z, 0.f); acc.w = fmaxf(acc.w, 0.f);
    }
    *(float4*)&dst[(size_t)s * F + f4] = acc;
}

// ---------------- hyperedge embedding (batched over graphs) ----------------
__global__ void hye_all_kernel(HyeArgs ha, const float* __restrict__ h2,
                               float* __restrict__ hye) {
    int g = blockIdx.y;
    int n = blockIdx.x * 16 + threadIdx.x / 16;
    if (n >= NN) return;
    const float* emb = h2 + (size_t)g * NN * DD2;
    float* dst = hye + (size_t)g * NN * DD2;
    const int* hnode = ha.hnode[g];
    int f4 = (threadIdx.x % 16) * 4;
    float4 acc = make_float4(0.f, 0.f, 0.f, 0.f);
    #pragma unroll
    for (int l = 0; l < LL; l++) {
        int v = hnode[n * LL + l];
        if (v > 0) {
            float4 e = *(const float4*)&emb[(size_t)(v - 1) * DD2 + f4];
            acc.x += e.x; acc.y += e.y; acc.z += e.z; acc.w += e.w;
        }
    }
    float s = 1.f / (ha.hlen[g][n] + 1e-15f);
    *(float4*)&dst[(size_t)n * DD2 + f4] =
        make_float4(acc.x * s, acc.y * s, acc.z * s, acc.w * s);
}

// ---------------- fusion attention (f32x2, 8 rows/iter) ----------------
struct AttnArgs {
    const float* z[8];
    const float* W1[2];
    const float* b1[2];
    const float* W2[2];
};

__global__ __launch_bounds__(128) void attn_kernel(AttnArgs a) {
    __shared__ float sW1[DD2 * HATT];
    __shared__ float sb[HATT];
    __shared__ float sW2[HATT];
    __shared__ __align__(16) float Zs[DD2][12];  // 8 rows used; stride 48B keeps 16B align
    __shared__ float red[128];
    int comp = blockIdx.y;
    int head = comp >> 2;
    const float* z = a.z[comp];
    int t = threadIdx.x;
    for (int i = t; i < DD2 * HATT; i += 128) sW1[i] = a.W1[head][i];
    sb[t]  = a.b1[head][t];
    sW2[t] = a.W2[head][t];
    __syncthreads();

    float acc = 0.f;
    float w2 = sW2[t];
    u64 bdup = pack_dup(sb[t]);
    for (int row0 = blockIdx.x * 8; row0 < NN; row0 += gridDim.x * 8) {
        #pragma unroll
        for (int j = 0; j < 4; j++) {
            int idx = t + 128 * j;        // 0..511
            int f = idx & 63, r = idx >> 6;
            Zs[f][r] = z[(size_t)(row0 + r) * DD2 + f];
        }
        __syncthreads();
        u64 hp[4];
        #pragma unroll
        for (int i = 0; i < 4; i++) hp[i] = bdup;
        #pragma unroll 8
        for (int f = 0; f < DD2; f++) {
            u64 wd = pack_dup(sW1[f * HATT + t]);
            ulonglong2 z01 = *(const ulonglong2*)&Zs[f][0];
            ulonglong2 z23 = *(const ulonglong2*)&Zs[f][4];
            fma2(hp[0], z01.x, wd);
            fma2(hp[1], z01.y, wd);
            fma2(hp[2], z23.x, wd);
            fma2(hp[3], z23.y, wd);
        }
        #pragma unroll
        for (int i = 0; i < 4; i++) {
            float2 h = unpack2(hp[i]);
            acc += (tanhf(h.x) + tanhf(h.y)) * w2;
        }
        __syncthreads();
    }
    red[t] = acc;
    __syncthreads();
    #pragma unroll
    for (int o = 64; o > 0; o >>= 1) {
        if (t < o) red[t] += red[t + o];
        __syncthreads();
    }
    if (t == 0) atomicAdd(&g_S[comp], red[0]);
}

__global__ void softmax_kernel() {
    if (threadIdx.x == 0 && blockIdx.x == 0) {
        for (int h = 0; h < 2; h++) {
            float v[4];
            float m = -1e30f;
            for (int k = 0; k < 4; k++) { v[k] = g_S[4 * h + k] / (float)NN; m = fmaxf(m, v[k]); }
            float s = 0.f;
            for (int k = 0; k < 4; k++) { v[k] = expf(v[k] - m); s += v[k]; }
            for (int k = 0; k < 4; k++) g_beta[4 * h + k] = v[k] / s;
        }
    }
}

__global__ void combine_kernel(float* __restrict__ out) {
    int idx = blockIdx.x * 256 + threadIdx.x;
    if (idx >= NN * DD2) return;
    __shared__ float b[8];
    if (threadIdx.x < 8) b[threadIdx.x] = g_beta[threadIdx.x];
    __syncthreads();
    const size_t S = (size_t)NN * DD2;
    float c = b[0] * g_h2[1 * S + idx] + b[1] * g_hye[0 * S + idx]
            + b[2] * g_h2[2 * S + idx] + b[3] * g_hye[2 * S + idx];
    float m = b[4] * g_h2[0 * S + idx] + b[5] * g_hye[1 * S + idx]
            + b[6] * g_h2[3 * S + idx] + b[7] * g_hye[3 * S + idx];
    out[idx]     = c;
    out[S + idx] = m;
}

// ---------------- host launcher ----------------
extern "C" void kernel_launch(void* const* d_in, const int* in_sizes, int n_in,
                              void* d_out, int out_size) {
    (void)out_size;

    // ---- input resolution by element count (order-agnostic) ----
    const float* x[4]     = {0,0,0,0};
    const int*   ei[4]    = {0,0,0,0};
    const float* hlen[4]  = {0,0,0,0};
    const int*   hnode[4] = {0,0,0,0};
    const float *W1 = 0, *b1 = 0, *W2 = 0, *b2 = 0;
    const float *aW1[2] = {0,0};
    const float *p128[4] = {0,0,0,0};
    int cx = 0, cei = 0, chn = 0, chl = 0, caw = 0, c128 = 0;
    for (int i = 0; i < n_in; i++) {
        int sz = in_sizes[i];
        const void* p = d_in[i];
        if      (sz == NN * FIN   && cx  < 4) x[cx++]      = (const float*)p;
        else if (sz == 2 * EE     && cei < 4) ei[cei++]    = (const int*)p;
        else if (sz == NN * LL    && chn < 4) hnode[chn++] = (const int*)p;
        else if (sz == NN         && chl < 4) hlen[chl++]  = (const float*)p;
        else if (sz == FIN * DD1)             W1 = (const float*)p;
        else if (sz == DD1)                   b1 = (const float*)p;
        else if (sz == DD1 * DD2)             W2 = (const float*)p;
        else if (sz == DD2)                   b2 = (const float*)p;
        else if (sz == DD2 * HATT && caw < 2) aW1[caw++]   = (const float*)p;
        else if (sz == HATT       && c128< 4) p128[c128++] = (const float*)p;
    }
    const float* ac_W1 = aW1[0];
    const float* am_W1 = aW1[1];
    const float* ac_b1 = p128[0];
    const float* ac_W2 = p128[1];
    const float* am_b1 = p128[2];
    const float* am_W2 = p128[3];
    float* out = (float*)d_out;

    float *p_y, *p_ef, *p_h1, *p_xw2, *p_h2, *p_hye, *p_binv, *p_dinv, *p_S;
    int *p_deg_e, *p_deg_n, *p_rp_e, *p_rp_n, *p_cur_e, *p_cur_n, *p_adj_e, *p_adj_n;
    cudaGetSymbolAddress((void**)&p_y,    g_y);
    cudaGetSymbolAddress((void**)&p_ef,   g_ef);
    cudaGetSymbolAddress((void**)&p_h1,   g_h1);
    cudaGetSymbolAddress((void**)&p_xw2,  g_xw2);
    cudaGetSymbolAddress((void**)&p_h2,   g_h2);
    cudaGetSymbolAddress((void**)&p_hye,  g_hye);
    cudaGetSymbolAddress((void**)&p_binv, g_binv);
    cudaGetSymbolAddress((void**)&p_dinv, g_dinv);
    cudaGetSymbolAddress((void**)&p_S,    g_S);
    cudaGetSymbolAddress((void**)&p_deg_e, g_deg_e);
    cudaGetSymbolAddress((void**)&p_deg_n, g_deg_n);
    cudaGetSymbolAddress((void**)&p_rp_e,  g_rp_e);
    cudaGetSymbolAddress((void**)&p_rp_n,  g_rp_n);
    cudaGetSymbolAddress((void**)&p_cur_e, g_cur_e);
    cudaGetSymbolAddress((void**)&p_cur_n, g_cur_n);
    cudaGetSymbolAddress((void**)&p_adj_e, g_adj_e);
    cudaGetSymbolAddress((void**)&p_adj_n, g_adj_n);

    const size_t SL  = (size_t)NN * DD2;
    const size_t SLY = (size_t)NN * FIN;
    const size_t SH1 = (size_t)NN * DD1;
    const int gridE = ceil_div(EE, 256);

    EiArgs ea;
    for (int g = 0; g < 4; g++) { ea.nidx[g] = ei[g]; ea.eidx[g] = ei[g] + EE; }

    // --- CSR build: all 4 graphs batched ---
    zero_all_kernel<<<ceil_div(4 * NN, 256), 256>>>(p_deg_e, p_deg_n, p_S);
    hist2_all_kernel<<<dim3(gridE, 4), 256>>>(ea, p_deg_n, p_deg_e);
    scan_local_all_kernel<<<dim3(NB, 8), 1024>>>(p_deg_e, p_deg_n, p_rp_e, p_rp_n);
    scan_spine_all_kernel<<<8, 64>>>();
    scan_add_all_kernel<<<dim3(NB, 8), 1024>>>(p_deg_e, p_deg_n, p_rp_e, p_rp_n,
                                               p_cur_e, p_cur_n, p_binv, p_dinv);
    scatter2_all_kernel<<<dim3(gridE, 4), 256>>>(ea, p_cur_e, p_cur_n, p_adj_e, p_adj_n);

    // --- conv1 gathers (per graph, keeps sources L2-resident): y = Dinv H Binv H^T x ---
    for (int g = 0; g < 4; g++) {
        seg_gather_kernel<FIN, false, false><<<ceil_div(NN, 8), 256>>>(
            p_adj_e + (size_t)g * EE, p_rp_e + g * (NN + 1), p_binv + g * NN,
            x[g], p_ef, (const float*)0, NN);
        seg_gather_kernel<FIN, false, false><<<ceil_div(NN, 8), 256>>>(
            p_adj_n + (size_t)g * EE, p_rp_n + g * (NN + 1), p_dinv + g * NN,
            p_ef, p_y + g * SLY, (const float*)0, NN);
    }

    // --- batched GEMMs across graphs ---
    GemmB g1, g2;
    for (int g = 0; g < 4; g++) {
        g1.A[g] = p_y + g * SLY;  g1.C[g] = p_h1 + g * SH1;
        g2.A[g] = p_h1 + g * SH1; g2.C[g] = p_xw2 + g * SL;
    }
    sgemm_kernel<128, 128, true><<<dim3(DD1 / 128, ceil_div(NN, 128), 4), 256>>>(
        g1, W1, b1, NN, FIN, DD1);
    sgemm_kernel<256, 64, false><<<dim3(1, ceil_div(NN, 256), 4), 256>>>(
        g2, W2, (const float*)0, NN, DD1, DD2);

    // --- conv2 gathers (per graph) ---
    for (int g = 0; g < 4; g++) {
        seg_gather_kernel<DD2, false, false><<<ceil_div(NN, 16), 256>>>(
            p_adj_e + (size_t)g * EE, p_rp_e + g * (NN + 1), p_binv + g * NN,
            p_xw2 + g * SL, p_ef, (const float*)0, NN);
        seg_gather_kernel<DD2, true, true><<<ceil_div(NN, 16), 256>>>(
            p_adj_n + (size_t)g * EE, p_rp_n + g * (NN + 1), p_dinv + g * NN,
            p_ef, p_h2 + g * SL, b2, NN);
    }

    // --- hyperedge embedding (batched) ---
    HyeArgs ha;
    for (int g = 0; g < 4; g++) { ha.hnode[g] = hnode[g]; ha.hlen[g] = hlen[g]; }
    hye_all_kernel<<<dim3(ceil_div(NN, 16), 4), 256>>>(ha, p_h2, p_hye);

    // --- fusion attention ---
    AttnArgs a;
    a.z[0] = p_h2  + 1 * SL;  // x1_mc
    a.z[1] = p_hye + 0 * SL;  // x2_cm
    a.z[2] = p_h2  + 2 * SL;  // x1_cc
    a.z[3] = p_hye + 2 * SL;  // x2_cc
    a.z[4] = p_h2  + 0 * SL;  // x1_cm
    a.z[5] = p_hye + 1 * SL;  // x2_mc
    a.z[6] = p_h2  + 3 * SL;  // x1_mm
    a.z[7] = p_hye + 3 * SL;  // x2_mm
    a.W1[0] = ac_W1; a.b1[0] = ac_b1; a.W2[0] = ac_W2;
    a.W1[1] = am_W1; a.b1[1] = am_b1; a.W2[1] = am_W2;
    attn_kernel<<<dim3(148, 8), 128>>>(a);
    softmax_kernel<<<1, 32>>>();
    combine_kernel<<<ceil_div(NN * DD2, 256), 256>>>(out);
}

// round 10
// speedup vs baseline: 2.5313x; 1.1779x over previous
#include <cuda_runtime.h>
#include <cuda_fp16.h>
#include <math.h>
#include <stdint.h>
#include <stddef.h>

#define NN   50000
#define EE   800000
#define LL   16
#define FIN  128
#define DD1  256
#define DD2  64
#define HATT 128
#define NB   49        // ceil(NN / 1024) scan blocks

typedef unsigned long long u64;

// ---------------- f32x2 packed helpers (sm_103a) ----------------
__device__ __forceinline__ u64 pack_dup(float a) {
    u64 d; unsigned int ai = __float_as_uint(a);
    asm("mov.b64 %0, {%1, %1};" : "=l"(d) : "r"(ai));
    return d;
}
__device__ __forceinline__ void fma2(u64& d, u64 a, u64 b) {
    asm("fma.rn.f32x2 %0, %1, %2, %0;" : "+l"(d) : "l"(a), "l"(b));
}
__device__ __forceinline__ float2 unpack2(u64 v) {
    unsigned int lo, hi;
    asm("mov.b64 {%0, %1}, %2;" : "=r"(lo), "=r"(hi) : "l"(v));
    return make_float2(__uint_as_float(lo), __uint_as_float(hi));
}
__device__ __forceinline__ float2 h2f(unsigned int u) {
    __half2 h = *reinterpret_cast<__half2*>(&u);
    return __half22float2(h);
}

// ---------------- device scratch (no allocations allowed) ----------------
__device__ __half g_xh [4 * NN * FIN];   // x in fp16 per graph
__device__ __half g_efh[4 * NN * FIN];   // edge features fp16 (conv1 F=128 / conv2 F=64 reuse)
__device__ __half g_xw2h[4 * NN * DD2];  // h1 @ W2 in fp16 per graph
__device__ float g_y  [4 * NN * FIN];    // double-gathered x per graph (fp32, GEMM1 input)
__device__ float g_h1 [4 * NN * DD1];    // conv1 outputs per graph
__device__ float g_h2 [4 * NN * DD2];    // conv2 outputs per graph
__device__ float g_hye[4 * NN * DD2];    // hyperedge embeddings per graph
__device__ int   g_deg_e[4 * NN], g_deg_n[4 * NN];
__device__ int   g_rp_e[4 * (NN + 1)], g_rp_n[4 * (NN + 1)];
__device__ int   g_cur_e[4 * NN], g_cur_n[4 * NN];
__device__ int   g_adj_e[4 * EE], g_adj_n[4 * EE];
__device__ float g_binv[4 * NN], g_dinv[4 * NN];
__device__ int   g_bsum[8][64];
__device__ float g_S[8];
__device__ float g_beta[8];

static inline int ceil_div(int a, int b) { return (a + b - 1) / b; }

struct EiArgs { const int* nidx[4]; const int* eidx[4]; };
struct HyeArgs { const int* hnode[4]; const float* hlen[4]; };
struct GemmB { const float* A[4]; void* C[4]; };
struct XPtrs { const float* x[4]; };
struct GB { const int* adj[4]; const int* rp[4]; const float* inv[4];
            const void* src[4]; void* dst[4]; };

// ---------------- CSR build (batched over 4 graphs) ----------------
__global__ void zero_all_kernel(int* de, int* dn, float* s) {
    int i = blockIdx.x * 256 + threadIdx.x;
    if (i < 4 * NN) { de[i] = 0; dn[i] = 0; }
    if (blockIdx.x == 0 && threadIdx.x < 8) s[threadIdx.x] = 0.f;
}

__global__ void hist2_all_kernel(EiArgs a, int* __restrict__ dn, int* __restrict__ de) {
    int g = blockIdx.y;
    int p = blockIdx.x * 256 + threadIdx.x;
    if (p < EE) {
        atomicAdd(&dn[g * NN + a.nidx[g][p]], 1);
        atomicAdd(&de[g * NN + a.eidx[g][p]], 1);
    }
}

__device__ __forceinline__ int block_scan_excl(int v, int* total_out) {
    __shared__ int wsum[32];
    int tid = threadIdx.x, lane = tid & 31, w = tid >> 5;
    int nw = blockDim.x >> 5;
    int inc = v;
    #pragma unroll
    for (int o = 1; o < 32; o <<= 1) {
        int t = __shfl_up_sync(0xffffffffu, inc, o);
        if (lane >= o) inc += t;
    }
    if (lane == 31) wsum[w] = inc;
    __syncthreads();
    if (w == 0) {
        int x = (lane < nw) ? wsum[lane] : 0;
        #pragma unroll
        for (int o = 1; o < 32; o <<= 1) {
            int t = __shfl_up_sync(0xffffffffu, x, o);
            if (lane >= o) x += t;
        }
        wsum[lane] = x;
    }
    __syncthreads();
    int prefix = (w > 0) ? wsum[w - 1] : 0;
    *total_out = wsum[nw - 1];
    int r = prefix + inc - v;
    __syncthreads();
    return r;
}

// y in [0,8): kind = y>>2 (0=e,1=n), graph = y&3
__global__ void scan_local_all_kernel(const int* __restrict__ de, const int* __restrict__ dn,
                                      int* __restrict__ rpe, int* __restrict__ rpn) {
    int y = blockIdx.y;
    int g = y & 3, kind = y >> 2;
    const int* deg = (kind ? dn : de) + g * NN;
    int* rp = (kind ? rpn : rpe) + g * (NN + 1);
    int i = blockIdx.x * 1024 + threadIdx.x;
    int v = (i < NN) ? deg[i] : 0;
    int total;
    int ex = block_scan_excl(v, &total);
    if (i < NN) rp[i] = ex;
    if (threadIdx.x == 0) g_bsum[y][blockIdx.x] = total;
}

__global__ void scan_spine_all_kernel() {
    int y = blockIdx.x;
    int t = threadIdx.x;
    int v = (t < NB) ? g_bsum[y][t] : 0;
    int total;
    int ex = block_scan_excl(v, &total);
    if (t < NB) g_bsum[y][t] = ex;
}

__global__ void scan_add_all_kernel(const int* __restrict__ de, const int* __restrict__ dn,
                                    int* __restrict__ rpe, int* __restrict__ rpn,
                                    int* __restrict__ cure, int* __restrict__ curn,
                                    float* __restrict__ binv, float* __restrict__ dinv) {
    int y = blockIdx.y;
    int g = y & 3, kind = y >> 2;
    int i = blockIdx.x * 1024 + threadIdx.x;
    if (i >= NN) return;
    int off = g_bsum[y][blockIdx.x];
    const int* deg = (kind ? dn : de) + g * NN;
    int* rp  = (kind ? rpn : rpe) + g * (NN + 1);
    int* cur = (kind ? curn : cure) + g * NN;
    float* inv = (kind ? dinv : binv) + g * NN;
    int r = rp[i] + off;
    rp[i] = r; cur[i] = r;
    int d = deg[i];
    inv[i] = (d > 0) ? (1.f / (float)d) : 0.f;
    if (i == NN - 1) rp[NN] = r + d;
}

__global__ void scatter2_all_kernel(EiArgs a, int* __restrict__ cure, int* __restrict__ curn,
                                    int* __restrict__ adje, int* __restrict__ adjn) {
    int g = blockIdx.y;
    int p = blockIdx.x * 256 + threadIdx.x;
    if (p >= EE) return;
    int nv = a.nidx[g][p], ev = a.eidx[g][p];
    int pe = atomicAdd(&cure[g * NN + ev], 1); adje[(size_t)g * EE + pe] = nv;
    int pn = atomicAdd(&curn[g * NN + nv], 1); adjn[(size_t)g * EE + pn] = ev;
}

// ---------------- fp32 -> fp16 conversion (batched) ----------------
__global__ void f2h_kernel(XPtrs xp, __half* __restrict__ dst) {
    int g = blockIdx.y;
    int i = blockIdx.x * 256 + threadIdx.x;        // group of 8 floats
    if (i >= NN * FIN / 8) return;
    const float* x = xp.x[g];
    size_t base = (size_t)i * 8;
    float4 a = *(const float4*)&x[base];
    float4 b = *(const float4*)&x[base + 4];
    __half2 h[4];
    h[0] = __floats2half2_rn(a.x, a.y);
    h[1] = __floats2half2_rn(a.z, a.w);
    h[2] = __floats2half2_rn(b.x, b.y);
    h[3] = __floats2half2_rn(b.z, b.w);
    *(uint4*)&dst[(size_t)g * NN * FIN + base] = *(uint4*)h;
}

// ---------------- segment gather on fp16 rows, batched over graphs ----------------
template<int F, bool RELU, bool BIAS, bool OUTH>
__global__ __launch_bounds__(256) void seg_gather_h_kernel(GB gb, const float* __restrict__ bias) {
    constexpr int T = F / 8;            // threads per segment (8 halves each)
    constexpr int SPB = 256 / T;
    int g = blockIdx.y;
    int s = blockIdx.x * SPB + threadIdx.x / T;
    if (s >= NN) return;
    int f8 = (threadIdx.x % T) * 8;
    const int* __restrict__ adj = gb.adj[g];
    const __half* __restrict__ src = (const __half*)gb.src[g];
    const int* rp = gb.rp[g];
    int beg = rp[s], end = rp[s + 1];
    float ax[8];
    #pragma unroll
    for (int k = 0; k < 8; k++) ax[k] = 0.f;
    int i = beg;
    for (; i + 2 <= end; i += 2) {
        int j0 = adj[i], j1 = adj[i + 1];
        uint4 v0 = *(const uint4*)&src[(size_t)j0 * F + f8];
        uint4 v1 = *(const uint4*)&src[(size_t)j1 * F + f8];
        unsigned int w0[4] = {v0.x, v0.y, v0.z, v0.w};
        unsigned int w1[4] = {v1.x, v1.y, v1.z, v1.w};
        #pragma unroll
        for (int k = 0; k < 4; k++) {
            float2 f0 = h2f(w0[k]);
            float2 f1 = h2f(w1[k]);
            ax[2*k]   += f0.x + f1.x;
            ax[2*k+1] += f0.y + f1.y;
        }
    }
    if (i < end) {
        uint4 v0 = *(const uint4*)&src[(size_t)adj[i] * F + f8];
        unsigned int w0[4] = {v0.x, v0.y, v0.z, v0.w};
        #pragma unroll
        for (int k = 0; k < 4; k++) {
            float2 f0 = h2f(w0[k]);
            ax[2*k] += f0.x; ax[2*k+1] += f0.y;
        }
    }
    float sc = gb.inv[g][s];
    #pragma unroll
    for (int k = 0; k < 8; k++) ax[k] *= sc;
    if (BIAS) {
        #pragma unroll
        for (int k = 0; k < 8; k++) ax[k] += bias[f8 + k];
    }
    if (RELU) {
        #pragma unroll
        for (int k = 0; k < 8; k++) ax[k] = fmaxf(ax[k], 0.f);
    }
    if (OUTH) {
        __half* dst = (__half*)gb.dst[g];
        __half2 h[4];
        #pragma unroll
        for (int k = 0; k < 4; k++) h[k] = __floats2half2_rn(ax[2*k], ax[2*k+1]);
        *(uint4*)&dst[(size_t)s * F + f8] = *(uint4*)h;
    } else {
        float* dst = (float*)gb.dst[g];
        *(float4*)&dst[(size_t)s * F + f8]     = make_float4(ax[0], ax[1], ax[2], ax[3]);
        *(float4*)&dst[(size_t)s * F + f8 + 4] = make_float4(ax[4], ax[5], ax[6], ax[7]);
    }
}

// ---------------- SGEMM (f32x2 packed), batched over graphs via blockIdx.z ----------------
template<int BM, int BN, bool EPI, bool HOUT>
__global__ __launch_bounds__(256) void sgemm_kernel(
    GemmB gp, const float* __restrict__ B, const float* __restrict__ bias,
    int M, int K, int Nc)
{
    constexpr int BK = 16;
    constexpr int A_PT = BM * BK / (4 * 256);
    constexpr int B_PT = BK * BN / (4 * 256);
    constexpr int TX = BN / 8;
    __shared__ __align__(16) float As[BK][BM + 4];
    __shared__ __align__(16) float Bs[BK][BN + 4];
    const float* __restrict__ A = gp.A[blockIdx.z];
    const int bm = blockIdx.y * BM, bn = blockIdx.x * BN;
    const int tid = threadIdx.x;
    const int tx = tid % TX, ty = tid / TX;

    float4 aReg[A_PT], bReg[B_PT];
    #pragma unroll
    for (int p = 0; p < A_PT; p++) {
        int idx = tid + p * 256;
        int r = idx >> 2, kq = (idx & 3) * 4;
        int row = bm + r;
        aReg[p] = (row < M) ? *(const float4*)&A[(size_t)row * K + kq]
                            : make_float4(0.f, 0.f, 0.f, 0.f);
    }
    #pragma unroll
    for (int p = 0; p < B_PT; p++) {
        int idx = tid + p * 256;
        int kr = idx / (BN / 4), nq = (idx % (BN / 4)) * 4;
        bReg[p] = *(const float4*)&B[(size_t)kr * Nc + bn + nq];
    }

    u64 acc[8][4];
    #pragma unroll
    for (int i = 0; i < 8; i++)
        #pragma unroll
        for (int j = 0; j < 4; j++) acc[i][j] = 0ull;

    const int nk = K / BK;
    for (int t = 0; t < nk; t++) {
        #pragma unroll
        for (int p = 0; p < A_PT; p++) {
            int idx = tid + p * 256;
            int r = idx >> 2, kq = (idx & 3) * 4;
            As[kq + 0][r] = aReg[p].x;
            As[kq + 1][r] = aReg[p].y;
            As[kq + 2][r] = aReg[p].z;
            As[kq + 3][r] = aReg[p].w;
        }
        #pragma unroll
        for (int p = 0; p < B_PT; p++) {
            int idx = tid + p * 256;
            int kr = idx / (BN / 4), nq = (idx % (BN / 4)) * 4;
            *(float4*)&Bs[kr][nq] = bReg[p];
        }
        __syncthreads();
        if (t + 1 < nk) {
            int k0 = (t + 1) * BK;
            #pragma unroll
            for (int p = 0; p < A_PT; p++) {
                int idx = tid + p * 256;
                int r = idx >> 2, kq = (idx & 3) * 4;
                int row = bm + r;
                aReg[p] = (row < M) ? *(const float4*)&A[(size_t)row * K + k0 + kq]
                                    : make_float4(0.f, 0.f, 0.f, 0.f);
            }
            #pragma unroll
            for (int p = 0; p < B_PT; p++) {
                int idx = tid + p * 256;
                int kr = idx / (BN / 4), nq = (idx % (BN / 4)) * 4;
                bReg[p] = *(const float4*)&B[(size_t)(k0 + kr) * Nc + bn + nq];
            }
        }
        #pragma unroll
        for (int k = 0; k < BK; k++) {
            float4 a0 = *(const float4*)&As[k][ty * 8];
            float4 a1 = *(const float4*)&As[k][ty * 8 + 4];
            ulonglong2 bb0 = *(const ulonglong2*)&Bs[k][tx * 8];
            ulonglong2 bb1 = *(const ulonglong2*)&Bs[k][tx * 8 + 4];
            float av[8] = {a0.x, a0.y, a0.z, a0.w, a1.x, a1.y, a1.z, a1.w};
            #pragma unroll
            for (int i = 0; i < 8; i++) {
                u64 ad = pack_dup(av[i]);
                fma2(acc[i][0], ad, bb0.x);
                fma2(acc[i][1], ad, bb0.y);
                fma2(acc[i][2], ad, bb1.x);
                fma2(acc[i][3], ad, bb1.y);
            }
        }
        __syncthreads();
    }

    int colb = bn + tx * 8;
    float bv[8];
    if (EPI) {
        #pragma unroll
        for (int j = 0; j < 8; j++) bv[j] = bias[colb + j];
    }
    #pragma unroll
    for (int i = 0; i < 8; i++) {
        int row = bm + ty * 8 + i;
        if (row < M) {
            float v[8];
            #pragma unroll
            for (int jp = 0; jp < 4; jp++) {
                float2 c = unpack2(acc[i][jp]);
                v[2 * jp] = c.x; v[2 * jp + 1] = c.y;
            }
            if (EPI) {
                #pragma unroll
                for (int j = 0; j < 8; j++) v[j] = fmaxf(v[j] + bv[j], 0.f);
            }
            if (HOUT) {
                __half* Ch = (__half*)gp.C[blockIdx.z];
                __half2 h[4];
                #pragma unroll
                for (int jp = 0; jp < 4; jp++)
                    h[jp] = __floats2half2_rn(v[2 * jp], v[2 * jp + 1]);
                *(uint4*)&Ch[(size_t)row * Nc + colb] = *(uint4*)h;
            } else {
                float* C = (float*)gp.C[blockIdx.z];
                *(float4*)&C[(size_t)row * Nc + colb]     = make_float4(v[0], v[1], v[2], v[3]);
                *(float4*)&C[(size_t)row * Nc + colb + 4] = make_float4(v[4], v[5], v[6], v[7]);
            }
        }
    }
}

// ---------------- hyperedge embedding (batched over graphs) ----------------
__global__ void hye_all_kernel(HyeArgs ha, const float* __restrict__ h2,
                               float* __restrict__ hye) {
    int g = blockIdx.y;
    int n = blockIdx.x * 16 + threadIdx.x / 16;
    if (n >= NN) return;
    const float* emb = h2 + (size_t)g * NN * DD2;
    float* dst = hye + (size_t)g * NN * DD2;
    const int* hnode = ha.hnode[g];
    int f4 = (threadIdx.x % 16) * 4;
    float4 acc = make_float4(0.f, 0.f, 0.f, 0.f);
    #pragma unroll
    for (int l = 0; l < LL; l++) {
        int v = hnode[n * LL + l];
        if (v > 0) {
            float4 e = *(const float4*)&emb[(size_t)(v - 1) * DD2 + f4];
            acc.x += e.x; acc.y += e.y; acc.z += e.z; acc.w += e.w;
        }
    }
    float s = 1.f / (ha.hlen[g][n] + 1e-15f);
    *(float4*)&dst[(size_t)n * DD2 + f4] =
        make_float4(acc.x * s, acc.y * s, acc.z * s, acc.w * s);
}

// ---------------- fusion attention (f32x2, 8 rows/iter) ----------------
struct AttnArgs {
    const float* z[8];
    const float* W1[2];
    const float* b1[2];
    const float* W2[2];
};

__global__ __launch_bounds__(128) void attn_kernel(AttnArgs a) {
    __shared__ float sW1[DD2 * HATT];
    __shared__ float sb[HATT];
    __shared__ float sW2[HATT];
    __shared__ __align__(16) float Zs[DD2][12];
    __shared__ float red[128];
    int comp = blockIdx.y;
    int head = comp >> 2;
    const float* z = a.z[comp];
    int t = threadIdx.x;
    for (int i = t; i < DD2 * HATT; i += 128) sW1[i] = a.W1[head][i];
    sb[t]  = a.b1[head][t];
    sW2[t] = a.W2[head][t];
    __syncthreads();

    float acc = 0.f;
    float w2 = sW2[t];
    u64 bdup = pack_dup(sb[t]);
    for (int row0 = blockIdx.x * 8; row0 < NN; row0 += gridDim.x * 8) {
        #pragma unroll
        for (int j = 0; j < 4; j++) {
            int idx = t + 128 * j;
            int f = idx & 63, r = idx >> 6;
            Zs[f][r] = z[(size_t)(row0 + r) * DD2 + f];
        }
        __syncthreads();
        u64 hp[4];
        #pragma unroll
        for (int i = 0; i < 4; i++) hp[i] = bdup;
        #pragma unroll 8
        for (int f = 0; f < DD2; f++) {
            u64 wd = pack_dup(sW1[f * HATT + t]);
            ulonglong2 z01 = *(const ulonglong2*)&Zs[f][0];
            ulonglong2 z23 = *(const ulonglong2*)&Zs[f][4];
            fma2(hp[0], z01.x, wd);
            fma2(hp[1], z01.y, wd);
            fma2(hp[2], z23.x, wd);
            fma2(hp[3], z23.y, wd);
        }
        #pragma unroll
        for (int i = 0; i < 4; i++) {
            float2 h = unpack2(hp[i]);
            acc += (tanhf(h.x) + tanhf(h.y)) * w2;
        }
        __syncthreads();
    }
    red[t] = acc;
    __syncthreads();
    #pragma unroll
    for (int o = 64; o > 0; o >>= 1) {
        if (t < o) red[t] += red[t + o];
        __syncthreads();
    }
    if (t == 0) atomicAdd(&g_S[comp], red[0]);
}

__global__ void softmax_kernel() {
    if (threadIdx.x == 0 && blockIdx.x == 0) {
        for (int h = 0; h < 2; h++) {
            float v[4];
            float m = -1e30f;
            for (int k = 0; k < 4; k++) { v[k] = g_S[4 * h + k] / (float)NN; m = fmaxf(m, v[k]); }
            float s = 0.f;
            for (int k = 0; k < 4; k++) { v[k] = expf(v[k] - m); s += v[k]; }
            for (int k = 0; k < 4; k++) g_beta[4 * h + k] = v[k] / s;
        }
    }
}

__global__ void combine_kernel(float* __restrict__ out) {
    int idx = blockIdx.x * 256 + threadIdx.x;
    if (idx >= NN * DD2) return;
    __shared__ float b[8];
    if (threadIdx.x < 8) b[threadIdx.x] = g_beta[threadIdx.x];
    __syncthreads();
    const size_t S = (size_t)NN * DD2;
    float c = b[0] * g_h2[1 * S + idx] + b[1] * g_hye[0 * S + idx]
            + b[2] * g_h2[2 * S + idx] + b[3] * g_hye[2 * S + idx];
    float m = b[4] * g_h2[0 * S + idx] + b[5] * g_hye[1 * S + idx]
            + b[6] * g_h2[3 * S + idx] + b[7] * g_hye[3 * S + idx];
    out[idx]     = c;
    out[S + idx] = m;
}

// ---------------- host launcher ----------------
extern "C" void kernel_launch(void* const* d_in, const int* in_sizes, int n_in,
                              void* d_out, int out_size) {
    (void)out_size;

    // ---- input resolution by element count (order-agnostic) ----
    const float* x[4]     = {0,0,0,0};
    const int*   ei[4]    = {0,0,0,0};
    const float* hlen[4]  = {0,0,0,0};
    const int*   hnode[4] = {0,0,0,0};
    const float *W1 = 0, *b1 = 0, *W2 = 0, *b2 = 0;
    const float *aW1[2] = {0,0};
    const float *p128[4] = {0,0,0,0};
    int cx = 0, cei = 0, chn = 0, chl = 0, caw = 0, c128 = 0;
    for (int i = 0; i < n_in; i++) {
        int sz = in_sizes[i];
        const void* p = d_in[i];
        if      (sz == NN * FIN   && cx  < 4) x[cx++]      = (const float*)p;
        else if (sz == 2 * EE     && cei < 4) ei[cei++]    = (const int*)p;
        else if (sz == NN * LL    && chn < 4) hnode[chn++] = (const int*)p;
        else if (sz == NN         && chl < 4) hlen[chl++]  = (const float*)p;
        else if (sz == FIN * DD1)             W1 = (const float*)p;
        else if (sz == DD1)                   b1 = (const float*)p;
        else if (sz == DD1 * DD2)             W2 = (const float*)p;
        else if (sz == DD2)                   b2 = (const float*)p;
        else if (sz == DD2 * HATT && caw < 2) aW1[caw++]   = (const float*)p;
        else if (sz == HATT       && c128< 4) p128[c128++] = (const float*)p;
    }
    const float* ac_W1 = aW1[0];
    const float* am_W1 = aW1[1];
    const float* ac_b1 = p128[0];
    const float* ac_W2 = p128[1];
    const float* am_b1 = p128[2];
    const float* am_W2 = p128[3];
    float* out = (float*)d_out;

    __half *p_xh, *p_efh, *p_xw2h;
    float *p_y, *p_h1, *p_h2, *p_hye, *p_binv, *p_dinv, *p_S;
    int *p_deg_e, *p_deg_n, *p_rp_e, *p_rp_n, *p_cur_e, *p_cur_n, *p_adj_e, *p_adj_n;
    cudaGetSymbolAddress((void**)&p_xh,   g_xh);
    cudaGetSymbolAddress((void**)&p_efh,  g_efh);
    cudaGetSymbolAddress((void**)&p_xw2h, g_xw2h);
    cudaGetSymbolAddress((void**)&p_y,    g_y);
    cudaGetSymbolAddress((void**)&p_h1,   g_h1);
    cudaGetSymbolAddress((void**)&p_h2,   g_h2);
    cudaGetSymbolAddress((void**)&p_hye,  g_hye);
    cudaGetSymbolAddress((void**)&p_binv, g_binv);
    cudaGetSymbolAddress((void**)&p_dinv, g_dinv);
    cudaGetSymbolAddress((void**)&p_S,    g_S);
    cudaGetSymbolAddress((void**)&p_deg_e, g_deg_e);
    cudaGetSymbolAddress((void**)&p_deg_n, g_deg_n);
    cudaGetSymbolAddress((void**)&p_rp_e,  g_rp_e);
    cudaGetSymbolAddress((void**)&p_rp_n,  g_rp_n);
    cudaGetSymbolAddress((void**)&p_cur_e, g_cur_e);
    cudaGetSymbolAddress((void**)&p_cur_n, g_cur_n);
    cudaGetSymbolAddress((void**)&p_adj_e, g_adj_e);
    cudaGetSymbolAddress((void**)&p_adj_n, g_adj_n);

    const size_t SL  = (size_t)NN * DD2;
    const size_t SLY = (size_t)NN * FIN;
    const size_t SH1 = (size_t)NN * DD1;
    const int gridE = ceil_div(EE, 256);

    EiArgs ea;
    for (int g = 0; g < 4; g++) { ea.nidx[g] = ei[g]; ea.eidx[g] = ei[g] + EE; }

    // --- CSR build: all 4 graphs batched ---
    zero_all_kernel<<<ceil_div(4 * NN, 256), 256>>>(p_deg_e, p_deg_n, p_S);
    hist2_all_kernel<<<dim3(gridE, 4), 256>>>(ea, p_deg_n, p_deg_e);
    scan_local_all_kernel<<<dim3(NB, 8), 1024>>>(p_deg_e, p_deg_n, p_rp_e, p_rp_n);
    scan_spine_all_kernel<<<8, 64>>>();
    scan_add_all_kernel<<<dim3(NB, 8), 1024>>>(p_deg_e, p_deg_n, p_rp_e, p_rp_n,
                                               p_cur_e, p_cur_n, p_binv, p_dinv);
    scatter2_all_kernel<<<dim3(gridE, 4), 256>>>(ea, p_cur_e, p_cur_n, p_adj_e, p_adj_n);

    // --- x -> fp16 (batched) ---
    XPtrs xp; for (int g = 0; g < 4; g++) xp.x[g] = x[g];
    f2h_kernel<<<dim3(ceil_div(NN * FIN / 8, 256), 4), 256>>>(xp, p_xh);

    // --- conv1 gathers, batched, fp16 rows: ef = Binv H^T x ; y = Dinv H ef ---
    GB gbe1, gbn1, gbe2, gbn2;
    for (int g = 0; g < 4; g++) {
        gbe1.adj[g] = p_adj_e + (size_t)g * EE;
        gbe1.rp[g]  = p_rp_e + g * (NN + 1);
        gbe1.inv[g] = p_binv + g * NN;
        gbe1.src[g] = p_xh + g * SLY;
        gbe1.dst[g] = p_efh + g * SLY;

        gbn1.adj[g] = p_adj_n + (size_t)g * EE;
        gbn1.rp[g]  = p_rp_n + g * (NN + 1);
        gbn1.inv[g] = p_dinv + g * NN;
        gbn1.src[g] = p_efh + g * SLY;
        gbn1.dst[g] = p_y + g * SLY;

        gbe2.adj[g] = gbe1.adj[g]; gbe2.rp[g] = gbe1.rp[g]; gbe2.inv[g] = gbe1.inv[g];
        gbe2.src[g] = p_xw2h + g * SL;
        gbe2.dst[g] = p_efh + g * SL;

        gbn2.adj[g] = gbn1.adj[g]; gbn2.rp[g] = gbn1.rp[g]; gbn2.inv[g] = gbn1.inv[g];
        gbn2.src[g] = p_efh + g * SL;
        gbn2.dst[g] = p_h2 + g * SL;
    }
    seg_gather_h_kernel<FIN, false, false, true ><<<dim3(ceil_div(NN, 16), 4), 256>>>(
        gbe1, (const float*)0);
    seg_gather_h_kernel<FIN, false, false, false><<<dim3(ceil_div(NN, 16), 4), 256>>>(
        gbn1, (const float*)0);

    // --- batched GEMMs across graphs ---
    GemmB g1, g2;
    for (int g = 0; g < 4; g++) {
        g1.A[g] = p_y + g * SLY;  g1.C[g] = p_h1 + g * SH1;
        g2.A[g] = p_h1 + g * SH1; g2.C[g] = p_xw2h + g * SL;
    }
    sgemm_kernel<128, 128, true, false><<<dim3(DD1 / 128, ceil_div(NN, 128), 4), 256>>>(
        g1, W1, b1, NN, FIN, DD1);
    sgemm_kernel<256, 64, false, true><<<dim3(1, ceil_div(NN, 256), 4), 256>>>(
        g2, W2, (const float*)0, NN, DD1, DD2);

    // --- conv2 gathers, batched, fp16 rows ---
    seg_gather_h_kernel<DD2, false, false, true ><<<dim3(ceil_div(NN, 32), 4), 256>>>(
        gbe2, (const float*)0);
    seg_gather_h_kernel<DD2, true, true, false><<<dim3(ceil_div(NN, 32), 4), 256>>>(
        gbn2, b2);

    // --- hyperedge embedding (batched) ---
    HyeArgs ha;
    for (int g = 0; g < 4; g++) { ha.hnode[g] = hnode[g]; ha.hlen[g] = hlen[g]; }
    hye_all_kernel<<<dim3(ceil_div(NN, 16), 4), 256>>>(ha, p_h2, p_hye);

    // --- fusion attention ---
    AttnArgs a;
    a.z[0] = p_h2  + 1 * SL;  // x1_mc
    a.z[1] = p_hye + 0 * SL;  // x2_cm
    a.z[2] = p_h2  + 2 * SL;  // x1_cc
    a.z[3] = p_hye + 2 * SL;  // x2_cc
    a.z[4] = p_h2  + 0 * SL;  // x1_cm
    a.z[5] = p_hye + 1 * SL;  // x2_mc
    a.z[6] = p_h2  + 3 * SL;  // x1_mm
    a.z[7] = p_hye + 3 * SL;  // x2_mm
    a.W1[0] = ac_W1; a.b1[0] = ac_b1; a.W2[0] = ac_W2;
    a.W1[1] = am_W1; a.b1[1] = am_b1; a.W2[1] = am_W2;
    attn_kernel<<<dim3(148, 8), 128>>>(a);
    softmax_kernel<<<1, 32>>>();
    combine_kernel<<<ceil_div(NN * DD2, 256), 256>>>(out);
}

// round 13
// speedup vs baseline: 3.3715x; 1.3319x over previous
#include <cuda_runtime.h>
#include <cuda_fp16.h>
#include <math.h>
#include <stdint.h>
#include <stddef.h>

#define NN   50000
#define EE   800000
#define LL   16
#define FIN  128
#define DD1  256
#define DD2  64
#define HATT 128
#define NB   49        // ceil(NN / 1024) scan blocks

typedef unsigned long long u64;

// ---------------- f32x2 packed helpers (sm_103a) ----------------
__device__ __forceinline__ u64 pack_dup(float a) {
    u64 d; unsigned int ai = __float_as_uint(a);
    asm("mov.b64 %0, {%1, %1};" : "=l"(d) : "r"(ai));
    return d;
}
__device__ __forceinline__ void fma2(u64& d, u64 a, u64 b) {
    asm("fma.rn.f32x2 %0, %1, %2, %0;" : "+l"(d) : "l"(a), "l"(b));
}
__device__ __forceinline__ float2 unpack2(u64 v) {
    unsigned int lo, hi;
    asm("mov.b64 {%0, %1}, %2;" : "=r"(lo), "=r"(hi) : "l"(v));
    return make_float2(__uint_as_float(lo), __uint_as_float(hi));
}
__device__ __forceinline__ float2 h2f(unsigned int u) {
    __half2 h = *reinterpret_cast<__half2*>(&u);
    return __half22float2(h);
}

// ---------------- HMMA helpers ----------------
__device__ __forceinline__ uint32_t s2u(const void* p) {
    return (uint32_t)__cvta_generic_to_shared(p);
}
__device__ __forceinline__ void ldsmA4(uint32_t* r, uint32_t addr) {
    asm volatile("ldmatrix.sync.aligned.m8n8.x4.shared.b16 {%0,%1,%2,%3}, [%4];"
        : "=r"(r[0]), "=r"(r[1]), "=r"(r[2]), "=r"(r[3]) : "r"(addr));
}
__device__ __forceinline__ void ldsmBT2(uint32_t* r, uint32_t addr) {
    asm volatile("ldmatrix.sync.aligned.m8n8.x2.trans.shared.b16 {%0,%1}, [%2];"
        : "=r"(r[0]), "=r"(r[1]) : "r"(addr));
}
__device__ __forceinline__ void mma16816(float* d, const uint32_t* a, const uint32_t* b) {
    asm volatile("mma.sync.aligned.m16n8k16.row.col.f32.f16.f16.f32 "
        "{%0,%1,%2,%3}, {%4,%5,%6,%7}, {%8,%9}, {%0,%1,%2,%3};"
        : "+f"(d[0]), "+f"(d[1]), "+f"(d[2]), "+f"(d[3])
        : "r"(a[0]), "r"(a[1]), "r"(a[2]), "r"(a[3]), "r"(b[0]), "r"(b[1]));
}

// ---------------- device scratch (no allocations allowed) ----------------
__device__ __half g_xh [4 * NN * FIN];   // x in fp16 per graph
__device__ __half g_efh[4 * NN * FIN];   // edge features fp16 (conv1 F=128 / conv2 F=64 reuse)
__device__ __half g_yh [4 * NN * FIN];   // double-gathered x, fp16 (GEMM1 A)
__device__ __half g_h1h[4 * NN * DD1];   // conv1 output fp16 (GEMM2 A)
__device__ __half g_xw2h[4 * NN * DD2];  // h1 @ W2 in fp16 per graph
__device__ __half g_W1h[FIN * DD1];
__device__ __half g_W2h[DD1 * DD2];
__device__ float g_h2 [4 * NN * DD2];    // conv2 outputs per graph (fp32)
__device__ float g_hye[4 * NN * DD2];    // hyperedge embeddings per graph
__device__ int   g_deg_e[4 * NN], g_deg_n[4 * NN];
__device__ int   g_rp_e[4 * (NN + 1)], g_rp_n[4 * (NN + 1)];
__device__ int   g_cur_e[4 * NN], g_cur_n[4 * NN];
__device__ int   g_adj_e[4 * EE], g_adj_n[4 * EE];
__device__ float g_binv[4 * NN], g_dinv[4 * NN];
__device__ int   g_bsum[8][64];
__device__ float g_S[8];
__device__ float g_beta[8];

static inline int ceil_div(int a, int b) { return (a + b - 1) / b; }

struct EiArgs { const int* nidx[4]; const int* eidx[4]; };
struct HyeArgs { const int* hnode[4]; const float* hlen[4]; };
struct GemmH { const __half* A[4]; __half* C[4]; };
struct XPtrs { const float* x[4]; };
struct GB { const int* adj[4]; const int* rp[4]; const float* inv[4];
            const void* src[4]; void* dst[4]; };

// ---------------- CSR build (batched over 4 graphs) ----------------
__global__ void zero_all_kernel(int* de, int* dn, float* s) {
    int i = blockIdx.x * 256 + threadIdx.x;
    if (i < 4 * NN) { de[i] = 0; dn[i] = 0; }
    if (blockIdx.x == 0 && threadIdx.x < 8) s[threadIdx.x] = 0.f;
}

__global__ void hist2_all_kernel(EiArgs a, int* __restrict__ dn, int* __restrict__ de) {
    int g = blockIdx.y;
    int p = blockIdx.x * 256 + threadIdx.x;
    if (p < EE) {
        atomicAdd(&dn[g * NN + a.nidx[g][p]], 1);
        atomicAdd(&de[g * NN + a.eidx[g][p]], 1);
    }
}

__device__ __forceinline__ int block_scan_excl(int v, int* total_out) {
    __shared__ int wsum[32];
    int tid = threadIdx.x, lane = tid & 31, w = tid >> 5;
    int nw = blockDim.x >> 5;
    int inc = v;
    #pragma unroll
    for (int o = 1; o < 32; o <<= 1) {
        int t = __shfl_up_sync(0xffffffffu, inc, o);
        if (lane >= o) inc += t;
    }
    if (lane == 31) wsum[w] = inc;
    __syncthreads();
    if (w == 0) {
        int x = (lane < nw) ? wsum[lane] : 0;
        #pragma unroll
        for (int o = 1; o < 32; o <<= 1) {
            int t = __shfl_up_sync(0xffffffffu, x, o);
            if (lane >= o) x += t;
        }
        wsum[lane] = x;
    }
    __syncthreads();
    int prefix = (w > 0) ? wsum[w - 1] : 0;
    *total_out = wsum[nw - 1];
    int r = prefix + inc - v;
    __syncthreads();
    return r;
}

// y in [0,8): kind = y>>2 (0=e,1=n), graph = y&3
__global__ void scan_local_all_kernel(const int* __restrict__ de, const int* __restrict__ dn,
                                      int* __restrict__ rpe, int* __restrict__ rpn) {
    int y = blockIdx.y;
    int g = y & 3, kind = y >> 2;
    const int* deg = (kind ? dn : de) + g * NN;
    int* rp = (kind ? rpn : rpe) + g * (NN + 1);
    int i = blockIdx.x * 1024 + threadIdx.x;
    int v = (i < NN) ? deg[i] : 0;
    int total;
    int ex = block_scan_excl(v, &total);
    if (i < NN) rp[i] = ex;
    if (threadIdx.x == 0) g_bsum[y][blockIdx.x] = total;
}

__global__ void scan_spine_all_kernel() {
    int y = blockIdx.x;
    int t = threadIdx.x;
    int v = (t < NB) ? g_bsum[y][t] : 0;
    int total;
    int ex = block_scan_excl(v, &total);
    if (t < NB) g_bsum[y][t] = ex;
}

__global__ void scan_add_all_kernel(const int* __restrict__ de, const int* __restrict__ dn,
                                    int* __restrict__ rpe, int* __restrict__ rpn,
                                    int* __restrict__ cure, int* __restrict__ curn,
                                    float* __restrict__ binv, float* __restrict__ dinv) {
    int y = blockIdx.y;
    int g = y & 3, kind = y >> 2;
    int i = blockIdx.x * 1024 + threadIdx.x;
    if (i >= NN) return;
    int off = g_bsum[y][blockIdx.x];
    const int* deg = (kind ? dn : de) + g * NN;
    int* rp  = (kind ? rpn : rpe) + g * (NN + 1);
    int* cur = (kind ? curn : cure) + g * NN;
    float* inv = (kind ? dinv : binv) + g * NN;
    int r = rp[i] + off;
    rp[i] = r; cur[i] = r;
    int d = deg[i];
    inv[i] = (d > 0) ? (1.f / (float)d) : 0.f;
    if (i == NN - 1) rp[NN] = r + d;
}

__global__ void scatter2_all_kernel(EiArgs a, int* __restrict__ cure, int* __restrict__ curn,
                                    int* __restrict__ adje, int* __restrict__ adjn) {
    int g = blockIdx.y;
    int p = blockIdx.x * 256 + threadIdx.x;
    if (p >= EE) return;
    int nv = a.nidx[g][p], ev = a.eidx[g][p];
    int pe = atomicAdd(&cure[g * NN + ev], 1); adje[(size_t)g * EE + pe] = nv;
    int pn = atomicAdd(&curn[g * NN + nv], 1); adjn[(size_t)g * EE + pn] = ev;
}

// ---------------- fp32 -> fp16 conversion ----------------
__global__ void f2h_kernel(XPtrs xp, __half* __restrict__ dst) {
    int g = blockIdx.y;
    int i = blockIdx.x * 256 + threadIdx.x;        // group of 8 floats
    if (i >= NN * FIN / 8) return;
    const float* x = xp.x[g];
    size_t base = (size_t)i * 8;
    float4 a = *(const float4*)&x[base];
    float4 b = *(const float4*)&x[base + 4];
    __half2 h[4];
    h[0] = __floats2half2_rn(a.x, a.y);
    h[1] = __floats2half2_rn(a.z, a.w);
    h[2] = __floats2half2_rn(b.x, b.y);
    h[3] = __floats2half2_rn(b.z, b.w);
    *(uint4*)&dst[(size_t)g * NN * FIN + base] = *(uint4*)h;
}

__global__ void wconv_kernel(const float* __restrict__ W1, const float* __restrict__ W2,
                             __half* __restrict__ W1h, __half* __restrict__ W2h) {
    int i = blockIdx.x * 256 + threadIdx.x;
    if (i < FIN * DD1) W1h[i] = __float2half(W1[i]);
    if (i < DD1 * DD2) W2h[i] = __float2half(W2[i]);
}

// ---------------- segment gather on fp16 rows, batched over graphs ----------------
template<int F, bool RELU, bool BIAS, bool OUTH>
__global__ __launch_bounds__(256) void seg_gather_h_kernel(GB gb, const float* __restrict__ bias) {
    constexpr int T = F / 8;            // threads per segment (8 halves each)
    constexpr int SPB = 256 / T;
    int g = blockIdx.y;
    int s = blockIdx.x * SPB + threadIdx.x / T;
    if (s >= NN) return;
    int f8 = (threadIdx.x % T) * 8;
    const int* __restrict__ adj = gb.adj[g];
    const __half* __restrict__ src = (const __half*)gb.src[g];
    const int* rp = gb.rp[g];
    int beg = rp[s], end = rp[s + 1];
    float ax[8];
    #pragma unroll
    for (int k = 0; k < 8; k++) ax[k] = 0.f;
    int i = beg;
    for (; i + 2 <= end; i += 2) {
        int j0 = adj[i], j1 = adj[i + 1];
        uint4 v0 = *(const uint4*)&src[(size_t)j0 * F + f8];
        uint4 v1 = *(const uint4*)&src[(size_t)j1 * F + f8];
        unsigned int w0[4] = {v0.x, v0.y, v0.z, v0.w};
        unsigned int w1[4] = {v1.x, v1.y, v1.z, v1.w};
        #pragma unroll
        for (int k = 0; k < 4; k++) {
            float2 f0 = h2f(w0[k]);
            float2 f1 = h2f(w1[k]);
            ax[2*k]   += f0.x + f1.x;
            ax[2*k+1] += f0.y + f1.y;
        }
    }
    if (i < end) {
        uint4 v0 = *(const uint4*)&src[(size_t)adj[i] * F + f8];
        unsigned int w0[4] = {v0.x, v0.y, v0.z, v0.w};
        #pragma unroll
        for (int k = 0; k < 4; k++) {
            float2 f0 = h2f(w0[k]);
            ax[2*k] += f0.x; ax[2*k+1] += f0.y;
        }
    }
    float sc = gb.inv[g][s];
    #pragma unroll
    for (int k = 0; k < 8; k++) ax[k] *= sc;
    if (BIAS) {
        #pragma unroll
        for (int k = 0; k < 8; k++) ax[k] += bias[f8 + k];
    }
    if (RELU) {
        #pragma unroll
        for (int k = 0; k < 8; k++) ax[k] = fmaxf(ax[k], 0.f);
    }
    if (OUTH) {
        __half* dst = (__half*)gb.dst[g];
        __half2 h[4];
        #pragma unroll
        for (int k = 0; k < 4; k++) h[k] = __floats2half2_rn(ax[2*k], ax[2*k+1]);
        *(uint4*)&dst[(size_t)s * F + f8] = *(uint4*)h;
    } else {
        float* dst = (float*)gb.dst[g];
        *(float4*)&dst[(size_t)s * F + f8]     = make_float4(ax[0], ax[1], ax[2], ax[3]);
        *(float4*)&dst[(size_t)s * F + f8 + 4] = make_float4(ax[4], ax[5], ax[6], ax[7]);
    }
}

// ---------------- HMMA GEMM: C[M,Nc](f16) = A[M,K](f16) @ B[K,Nc](f16), fp32 accum ----------------
// 256 threads = 8 warps (4 m x 2 n). BM=128, BK=32. Warp tile 32 x (BN/2).
template<int BN, bool EPI>
__global__ __launch_bounds__(256) void hgemm_kernel(
    GemmH gp, const __half* __restrict__ Bw, const float* __restrict__ bias,
    int M, int K, int Nc)
{
    constexpr int BM = 128, BK = 32;
    constexpr int WN = BN / 2;
    constexpr int FN = WN / 8;
    __shared__ __align__(16) __half As[BM][BK + 8];
    __shared__ __align__(16) __half Bs[BK][BN + 8];
    const __half* __restrict__ A = gp.A[blockIdx.z];
    __half* __restrict__ C = gp.C[blockIdx.z];
    const int bm = blockIdx.y * BM, bn = blockIdx.x * BN;
    const int tid = threadIdx.x, lane = tid & 31, warp = tid >> 5;
    const int wm = warp & 3, wn = warp >> 2;

    float acc[2][FN][4];
    #pragma unroll
    for (int fm = 0; fm < 2; fm++)
        #pragma unroll
        for (int fn = 0; fn < FN; fn++)
            #pragma unroll
            for (int q = 0; q < 4; q++) acc[fm][fn][q] = 0.f;

    for (int k0 = 0; k0 < K; k0 += BK) {
        #pragma unroll
        for (int p = 0; p < BM * BK / (256 * 8); p++) {
            int idx = tid + p * 256;
            int r = idx / (BK / 8), c8 = (idx % (BK / 8)) * 8;
            int row = bm + r;
            uint4 v = make_uint4(0u, 0u, 0u, 0u);
            if (row < M) v = *(const uint4*)&A[(size_t)row * K + k0 + c8];
            *(uint4*)&As[r][c8] = v;
        }
        #pragma unroll
        for (int p = 0; p < BK * BN / (256 * 8); p++) {
            int idx = tid + p * 256;
            int r = idx / (BN / 8), c8 = (idx % (BN / 8)) * 8;
            *(uint4*)&Bs[r][c8] = *(const uint4*)&Bw[(size_t)(k0 + r) * Nc + bn + c8];
        }
        __syncthreads();
        #pragma unroll
        for (int ks = 0; ks < BK; ks += 16) {
            uint32_t af[2][4], bf[FN][2];
            #pragma unroll
            for (int fm = 0; fm < 2; fm++) {
                int mrow = wm * 32 + fm * 16 + (lane & 15);
                int kcol = ks + (lane >> 4) * 8;
                ldsmA4(af[fm], s2u(&As[mrow][kcol]));
            }
            #pragma unroll
            for (int fn = 0; fn < FN; fn++) {
                int krow = ks + (lane & 15);
                int ncol = wn * WN + fn * 8;
                ldsmBT2(bf[fn], s2u(&Bs[krow][ncol]));
            }
            #pragma unroll
            for (int fm = 0; fm < 2; fm++)
                #pragma unroll
                for (int fn = 0; fn < FN; fn++)
                    mma16816(acc[fm][fn], af[fm], bf[fn]);
        }
        __syncthreads();
    }

    int gid = lane >> 2, tig = lane & 3;
    #pragma unroll
    for (int fm = 0; fm < 2; fm++) {
        #pragma unroll
        for (int fn = 0; fn < FN; fn++) {
            int col = bn + wn * WN + fn * 8 + tig * 2;
            float b0 = 0.f, b1 = 0.f;
            if (EPI) { b0 = bias[col]; b1 = bias[col + 1]; }
            float v0 = acc[fm][fn][0], v1 = acc[fm][fn][1];
            float v2 = acc[fm][fn][2], v3 = acc[fm][fn][3];
            if (EPI) {
                v0 = fmaxf(v0 + b0, 0.f); v1 = fmaxf(v1 + b1, 0.f);
                v2 = fmaxf(v2 + b0, 0.f); v3 = fmaxf(v3 + b1, 0.f);
            }
            int row0 = bm + wm * 32 + fm * 16 + gid;
            int row1 = row0 + 8;
            if (row0 < M) *(__half2*)&C[(size_t)row0 * Nc + col] = __floats2half2_rn(v0, v1);
            if (row1 < M) *(__half2*)&C[(size_t)row1 * Nc + col] = __floats2half2_rn(v2, v3);
        }
    }
}

// ---------------- hyperedge embedding (batched over graphs) ----------------
__global__ void hye_all_kernel(HyeArgs ha, const float* __restrict__ h2,
                               float* __restrict__ hye) {
    int g = blockIdx.y;
    int n = blockIdx.x * 16 + threadIdx.x / 16;
    if (n >= NN) return;
    const float* emb = h2 + (size_t)g * NN * DD2;
    float* dst = hye + (size_t)g * NN * DD2;
    const int* hnode = ha.hnode[g];
    int f4 = (threadIdx.x % 16) * 4;
    float4 acc = make_float4(0.f, 0.f, 0.f, 0.f);
    #pragma unroll
    for (int l = 0; l < LL; l++) {
        int v = hnode[n * LL + l];
        if (v > 0) {
            float4 e = *(const float4*)&emb[(size_t)(v - 1) * DD2 + f4];
            acc.x += e.x; acc.y += e.y; acc.z += e.z; acc.w += e.w;
        }
    }
    float s = 1.f / (ha.hlen[g][n] + 1e-15f);
    *(float4*)&dst[(size_t)n * DD2 + f4] =
        make_float4(acc.x * s, acc.y * s, acc.z * s, acc.w * s);
}

// ---------------- fusion attention (f32x2, 8 rows/iter) ----------------
struct AttnArgs {
    const float* z[8];
    const float* W1[2];
    const float* b1[2];
    const float* W2[2];
};

__global__ __launch_bounds__(128) void attn_kernel(AttnArgs a) {
    __shared__ float sW1[DD2 * HATT];
    __shared__ float sb[HATT];
    __shared__ float sW2[HATT];
    __shared__ __align__(16) float Zs[DD2][12];
    __shared__ float red[128];
    int comp = blockIdx.y;
    int head = comp >> 2;
    const float* z = a.z[comp];
    int t = threadIdx.x;
    for (int i = t; i < DD2 * HATT; i += 128) sW1[i] = a.W1[head][i];
    sb[t]  = a.b1[head][t];
    sW2[t] = a.W2[head][t];
    __syncthreads();

    float acc = 0.f;
    float w2 = sW2[t];
    u64 bdup = pack_dup(sb[t]);
    for (int row0 = blockIdx.x * 8; row0 < NN; row0 += gridDim.x * 8) {
        #pragma unroll
        for (int j = 0; j < 4; j++) {
            int idx = t + 128 * j;
            int f = idx & 63, r = idx >> 6;
            Zs[f][r] = z[(size_t)(row0 + r) * DD2 + f];
        }
        __syncthreads();
        u64 hp[4];
        #pragma unroll
        for (int i = 0; i < 4; i++) hp[i] = bdup;
        #pragma unroll 8
        for (int f = 0; f < DD2; f++) {
            u64 wd = pack_dup(sW1[f * HATT + t]);
            ulonglong2 z01 = *(const ulonglong2*)&Zs[f][0];
            ulonglong2 z23 = *(const ulonglong2*)&Zs[f][4];
            fma2(hp[0], z01.x, wd);
            fma2(hp[1], z01.y, wd);
            fma2(hp[2], z23.x, wd);
            fma2(hp[3], z23.y, wd);
        }
        #pragma unroll
        for (int i = 0; i < 4; i++) {
            float2 h = unpack2(hp[i]);
            acc += (tanhf(h.x) + tanhf(h.y)) * w2;
        }
        __syncthreads();
    }
    red[t] = acc;
    __syncthreads();
    #pragma unroll
    for (int o = 64; o > 0; o >>= 1) {
        if (t < o) red[t] += red[t + o];
        __syncthreads();
    }
    if (t == 0) atomicAdd(&g_S[comp], red[0]);
}

__global__ void softmax_kernel() {
    if (threadIdx.x == 0 && blockIdx.x == 0) {
        for (int h = 0; h < 2; h++) {
            float v[4];
            float m = -1e30f;
            for (int k = 0; k < 4; k++) { v[k] = g_S[4 * h + k] / (float)NN; m = fmaxf(m, v[k]); }
            float s = 0.f;
            for (int k = 0; k < 4; k++) { v[k] = expf(v[k] - m); s += v[k]; }
            for (int k = 0; k < 4; k++) g_beta[4 * h + k] = v[k] / s;
        }
    }
}

__global__ void combine_kernel(float* __restrict__ out) {
    int idx = blockIdx.x * 256 + threadIdx.x;
    if (idx >= NN * DD2) return;
    __shared__ float b[8];
    if (threadIdx.x < 8) b[threadIdx.x] = g_beta[threadIdx.x];
    __syncthreads();
    const size_t S = (size_t)NN * DD2;
    float c = b[0] * g_h2[1 * S + idx] + b[1] * g_hye[0 * S + idx]
            + b[2] * g_h2[2 * S + idx] + b[3] * g_hye[2 * S + idx];
    float m = b[4] * g_h2[0 * S + idx] + b[5] * g_hye[1 * S + idx]
            + b[6] * g_h2[3 * S + idx] + b[7] * g_hye[3 * S + idx];
    out[idx]     = c;
    out[S + idx] = m;
}

// ---------------- host launcher ----------------
extern "C" void kernel_launch(void* const* d_in, const int* in_sizes, int n_in,
                              void* d_out, int out_size) {
    (void)out_size;

    // ---- input resolution by element count (order-agnostic) ----
    const float* x[4]     = {0,0,0,0};
    const int*   ei[4]    = {0,0,0,0};
    const float* hlen[4]  = {0,0,0,0};
    const int*   hnode[4] = {0,0,0,0};
    const float *W1 = 0, *b1 = 0, *W2 = 0, *b2 = 0;
    const float *aW1[2] = {0,0};
    const float *p128[4] = {0,0,0,0};
    int cx = 0, cei = 0, chn = 0, chl = 0, caw = 0, c128 = 0;
    for (int i = 0; i < n_in; i++) {
        int sz = in_sizes[i];
        const void* p = d_in[i];
        if      (sz == NN * FIN   && cx  < 4) x[cx++]      = (const float*)p;
        else if (sz == 2 * EE     && cei < 4) ei[cei++]    = (const int*)p;
        else if (sz == NN * LL    && chn < 4) hnode[chn++] = (const int*)p;
        else if (sz == NN         && chl < 4) hlen[chl++]  = (const float*)p;
        else if (sz == FIN * DD1)             W1 = (const float*)p;
        else if (sz == DD1)                   b1 = (const float*)p;
        else if (sz == DD1 * DD2)             W2 = (const float*)p;
        else if (sz == DD2)                   b2 = (const float*)p;
        else if (sz == DD2 * HATT && caw < 2) aW1[caw++]   = (const float*)p;
        else if (sz == HATT       && c128< 4) p128[c128++] = (const float*)p;
    }
    const float* ac_W1 = aW1[0];
    const float* am_W1 = aW1[1];
    const float* ac_b1 = p128[0];
    const float* ac_W2 = p128[1];
    const float* am_b1 = p128[2];
    const float* am_W2 = p128[3];
    float* out = (float*)d_out;

    __half *p_xh, *p_efh, *p_yh, *p_h1h, *p_xw2h, *p_W1h, *p_W2h;
    float *p_h2, *p_hye, *p_binv, *p_dinv, *p_S;
    int *p_deg_e, *p_deg_n, *p_rp_e, *p_rp_n, *p_cur_e, *p_cur_n, *p_adj_e, *p_adj_n;
    cudaGetSymbolAddress((void**)&p_xh,   g_xh);
    cudaGetSymbolAddress((void**)&p_efh,  g_efh);
    cudaGetSymbolAddress((void**)&p_yh,   g_yh);
    cudaGetSymbolAddress((void**)&p_h1h,  g_h1h);
    cudaGetSymbolAddress((void**)&p_xw2h, g_xw2h);
    cudaGetSymbolAddress((void**)&p_W1h,  g_W1h);
    cudaGetSymbolAddress((void**)&p_W2h,  g_W2h);
    cudaGetSymbolAddress((void**)&p_h2,   g_h2);
    cudaGetSymbolAddress((void**)&p_hye,  g_hye);
    cudaGetSymbolAddress((void**)&p_binv, g_binv);
    cudaGetSymbolAddress((void**)&p_dinv, g_dinv);
    cudaGetSymbolAddress((void**)&p_S,    g_S);
    cudaGetSymbolAddress((void**)&p_deg_e, g_deg_e);
    cudaGetSymbolAddress((void**)&p_deg_n, g_deg_n);
    cudaGetSymbolAddress((void**)&p_rp_e,  g_rp_e);
    cudaGetSymbolAddress((void**)&p_rp_n,  g_rp_n);
    cudaGetSymbolAddress((void**)&p_cur_e, g_cur_e);
    cudaGetSymbolAddress((void**)&p_cur_n, g_cur_n);
    cudaGetSymbolAddress((void**)&p_adj_e, g_adj_e);
    cudaGetSymbolAddress((void**)&p_adj_n, g_adj_n);

    const size_t SL  = (size_t)NN * DD2;
    const size_t SLY = (size_t)NN * FIN;
    const size_t SH1 = (size_t)NN * DD1;
    const int gridE = ceil_div(EE, 256);

    EiArgs ea;
    for (int g = 0; g < 4; g++) { ea.nidx[g] = ei[g]; ea.eidx[g] = ei[g] + EE; }

    // --- CSR build: all 4 graphs batched ---
    zero_all_kernel<<<ceil_div(4 * NN, 256), 256>>>(p_deg_e, p_deg_n, p_S);
    hist2_all_kernel<<<dim3(gridE, 4), 256>>>(ea, p_deg_n, p_deg_e);
    scan_local_all_kernel<<<dim3(NB, 8), 1024>>>(p_deg_e, p_deg_n, p_rp_e, p_rp_n);
    scan_spine_all_kernel<<<8, 64>>>();
    scan_add_all_kernel<<<dim3(NB, 8), 1024>>>(p_deg_e, p_deg_n, p_rp_e, p_rp_n,
                                               p_cur_e, p_cur_n, p_binv, p_dinv);
    scatter2_all_kernel<<<dim3(gridE, 4), 256>>>(ea, p_cur_e, p_cur_n, p_adj_e, p_adj_n);

    // --- conversions: x -> fp16 (batched), W1/W2 -> fp16 ---
    XPtrs xp; for (int g = 0; g < 4; g++) xp.x[g] = x[g];
    f2h_kernel<<<dim3(ceil_div(NN * FIN / 8, 256), 4), 256>>>(xp, p_xh);
    wconv_kernel<<<ceil_div(FIN * DD1, 256), 256>>>(W1, W2, p_W1h, p_W2h);

    // --- conv1 gathers (batched, fp16): ef = Binv H^T x ; y = Dinv H ef (fp16 out) ---
    GB gbe1, gbn1, gbe2, gbn2;
    for (int g = 0; g < 4; g++) {
        gbe1.adj[g] = p_adj_e + (size_t)g * EE;
        gbe1.rp[g]  = p_rp_e + g * (NN + 1);
        gbe1.inv[g] = p_binv + g * NN;
        gbe1.src[g] = p_xh + g * SLY;
        gbe1.dst[g] = p_efh + g * SLY;

        gbn1.adj[g] = p_adj_n + (size_t)g * EE;
        gbn1.rp[g]  = p_rp_n + g * (NN + 1);
        gbn1.inv[g] = p_dinv + g * NN;
        gbn1.src[g] = p_efh + g * SLY;
        gbn1.dst[g] = p_yh + g * SLY;

        gbe2.adj[g] = gbe1.adj[g]; gbe2.rp[g] = gbe1.rp[g]; gbe2.inv[g] = gbe1.inv[g];
        gbe2.src[g] = p_xw2h + g * SL;
        gbe2.dst[g] = p_efh + g * SL;

        gbn2.adj[g] = gbn1.adj[g]; gbn2.rp[g] = gbn1.rp[g]; gbn2.inv[g] = gbn1.inv[g];
        gbn2.src[g] = p_efh + g * SL;
        gbn2.dst[g] = p_h2 + g * SL;
    }
    seg_gather_h_kernel<FIN, false, false, true><<<dim3(ceil_div(NN, 16), 4), 256>>>(
        gbe1, (const float*)0);
    seg_gather_h_kernel<FIN, false, false, true><<<dim3(ceil_div(NN, 16), 4), 256>>>(
        gbn1, (const float*)0);

    // --- HMMA GEMMs (batched over graphs via blockIdx.z) ---
    GemmH g1, g2;
    for (int g = 0; g < 4; g++) {
        g1.A[g] = p_yh + g * SLY;  g1.C[g] = p_h1h + g * SH1;
        g2.A[g] = p_h1h + g * SH1; g2.C[g] = p_xw2h + g * SL;
    }
    hgemm_kernel<128, true><<<dim3(DD1 / 128, ceil_div(NN, 128), 4), 256>>>(
        g1, p_W1h, b1, NN, FIN, DD1);
    hgemm_kernel<64, false><<<dim3(1, ceil_div(NN, 128), 4), 256>>>(
        g2, p_W2h, (const float*)0, NN, DD1, DD2);

    // --- conv2 gathers (batched, fp16 rows) ---
    seg_gather_h_kernel<DD2, false, false, true><<<dim3(ceil_div(NN, 32), 4), 256>>>(
        gbe2, (const float*)0);
    seg_gather_h_kernel<DD2, true, true, false><<<dim3(ceil_div(NN, 32), 4), 256>>>(
        gbn2, b2);

    // --- hyperedge embedding (batched) ---
    HyeArgs ha;
    for (int g = 0; g < 4; g++) { ha.hnode[g] = hnode[g]; ha.hlen[g] = hlen[g]; }
    hye_all_kernel<<<dim3(ceil_div(NN, 16), 4), 256>>>(ha, p_h2, p_hye);

    // --- fusion attention ---
    AttnArgs a;
    a.z[0] = p_h2  + 1 * SL;  // x1_mc
    a.z[1] = p_hye + 0 * SL;  // x2_cm
    a.z[2] = p_h2  + 2 * SL;  // x1_cc
    a.z[3] = p_hye + 2 * SL;  // x2_cc
    a.z[4] = p_h2  + 0 * SL;  // x1_cm
    a.z[5] = p_hye + 1 * SL;  // x2_mc
    a.z[6] = p_h2  + 3 * SL;  // x1_mm
    a.z[7] = p_hye + 3 * SL;  // x2_mm
    a.W1[0] = ac_W1; a.b1[0] = ac_b1; a.W2[0] = ac_W2;
    a.W1[1] = am_W1; a.b1[1] = am_b1; a.W2[1] = am_W2;
    attn_kernel<<<dim3(148, 8), 128>>>(a);
    softmax_kernel<<<1, 32>>>();
    combine_kernel<<<ceil_div(NN * DD2, 256), 256>>>(out);
}